// round 7
// baseline (speedup 1.0000x reference)
#include <cuda_runtime.h>
#include <math.h>

#define NN 4
#define C1 128
#define C2 36
#define Hh 192
#define Ww 192
#define HO 190
#define WO 190
#define HW (Hh*Ww)
#define HWO (HO*WO)
#define PB 128
#define NT 288

typedef unsigned long long ull;

// Scratch (device globals: allocation-free rule)
__device__ float g_offset[NN*C2*HWO];       // offset conv output [N,36,HO,WO]
__device__ ull   g_wt2[9*2*64*C2];          // [t][dg][c][o] BN-scaled, pair-duplicated
__device__ float g_bias[C2];                // folded BN bias

// ---- packed f32x2 helpers -------------------------------------------------
__device__ __forceinline__ ull fma2(ull a, ull b, ull c) {
    ull d; asm("fma.rn.f32x2 %0,%1,%2,%3;" : "=l"(d) : "l"(a), "l"(b), "l"(c));
    return d;
}
__device__ __forceinline__ float lo2(ull a) { return __uint_as_float((unsigned)a); }
__device__ __forceinline__ float hi2(ull a) { return __uint_as_float((unsigned)(a >> 32)); }

// ---------------------------------------------------------------------------
// Prep: deform_w [o][c][3][3] -> g_wt2[t][dg][c][o] (dup pairs), BN fold.
// ---------------------------------------------------------------------------
__global__ void prep_kernel(const float* __restrict__ dw,
                            const float* __restrict__ gamma,
                            const float* __restrict__ beta,
                            const float* __restrict__ mean,
                            const float* __restrict__ var)
{
    int idx = blockIdx.x * 256 + threadIdx.x;
    if (idx < 9 * C1 * C2) {
        int t = idx / (C1 * C2);
        int r = idx % (C1 * C2);
        int c128 = r / C2, o = r % C2;
        int dg = c128 >> 6, c = c128 & 63;
        float s = gamma[o] * rsqrtf(var[o] + 1e-5f);
        float w = dw[(o * C1 + c128) * 9 + t] * s;
        unsigned wb = __float_as_uint(w);
        g_wt2[((size_t)(t * 2 + dg) * 64 + c) * C2 + o] =
            ((ull)wb << 32) | (ull)wb;
    }
    if (idx < C2) {
        float s = gamma[idx] * rsqrtf(var[idx] + 1e-5f);
        g_bias[idx] = beta[idx] - mean[idx] * s;
    }
}

// ---------------------------------------------------------------------------
// Offset-generating grouped conv (groups=4, VALID, 3x3) — known-good version.
// ---------------------------------------------------------------------------
__global__ __launch_bounds__(192) void offset_conv_kernel(
    const float* __restrict__ x, const float* __restrict__ cw)
{
    __shared__ float sx[32 * 8 * 34];
    __shared__ float ws[32 * 9 * 9];

    int n = blockIdx.z >> 2;
    int g = blockIdx.z & 3;
    int x0 = blockIdx.x * 32;
    int y0 = blockIdx.y * 6;
    int tid = threadIdx.x;

    for (int idx = tid; idx < 2592; idx += 192) {
        int o = idx % 9; int rem = idx / 9;
        int tap = rem % 9; int ci = rem / 9;
        ws[idx] = cw[((g * 9 + o) * 32 + ci) * 9 + tap];
    }

    const float* xb = x + ((size_t)n * C1 + g * 32) * HW;
    for (int idx = tid; idx < 32 * 8 * 34; idx += 192) {
        int ci = idx / 272;
        int r  = (idx % 272) / 34;
        int col = idx % 34;
        int gy = y0 + r, gx = x0 + col;
        float v = 0.f;
        if (gy < Hh && gx < Ww) v = xb[ci * HW + gy * Ww + gx];
        sx[idx] = v;
    }
    __syncthreads();

    int lx = tid & 31, ly = tid >> 5;
    float acc[9];
#pragma unroll
    for (int o = 0; o < 9; o++) acc[o] = 0.f;

    for (int ci = 0; ci < 32; ci++) {
        int base = ci * 272 + ly * 34 + lx;
#pragma unroll
        for (int tap = 0; tap < 9; tap++) {
            int i = tap / 3, j = tap % 3;
            float v = sx[base + i * 34 + j];
            const float* wp = &ws[(ci * 9 + tap) * 9];
#pragma unroll
            for (int o = 0; o < 9; o++) acc[o] = fmaf(v, wp[o], acc[o]);
        }
    }

    int yy = y0 + ly, xx = x0 + lx;
    if (yy < HO && xx < WO) {
        float* op = g_offset + ((size_t)n * C2 + g * 9) * HWO + yy * WO + xx;
#pragma unroll
        for (int o = 0; o < 9; o++) op[o * HWO] = acc[o];
    }
}

// ---------------------------------------------------------------------------
struct Ctx {
    int o00, o01, o10, o11;
    float W00, W01, W10, W11;
};

__device__ __forceinline__ Ctx make_ctx(int yy, int xx, int i, int j,
                                        float dy, float dx)
{
    Ctx c;
    float py = (float)(yy + i) + dy;
    float px = (float)(xx + j) + dx;
    float fy0 = floorf(py), fx0 = floorf(px);
    float wy1 = py - fy0, wx1 = px - fx0;
    float wy0 = 1.f - wy1, wx0 = 1.f - wx1;

    bool vy0 = (fy0       >= 0.f) && (fy0       <= (float)(Hh - 1));
    bool vy1 = (fy0 + 1.f >= 0.f) && (fy0 + 1.f <= (float)(Hh - 1));
    bool vx0 = (fx0       >= 0.f) && (fx0       <= (float)(Ww - 1));
    bool vx1 = (fx0 + 1.f >= 0.f) && (fx0 + 1.f <= (float)(Ww - 1));

    int y0i = (int)fy0, x0i = (int)fx0;
    int y0c = min(max(y0i,     0), Hh - 1);
    int y1c = min(max(y0i + 1, 0), Hh - 1);
    int x0c = min(max(x0i,     0), Ww - 1);
    int x1c = min(max(x0i + 1, 0), Ww - 1);

    c.W00 = wy0 * wx0 * ((vy0 && vx0) ? 1.f : 0.f);
    c.W01 = wy0 * wx1 * ((vy0 && vx1) ? 1.f : 0.f);
    c.W10 = wy1 * wx0 * ((vy1 && vx0) ? 1.f : 0.f);
    c.W11 = wy1 * wx1 * ((vy1 && vx1) ? 1.f : 0.f);

    c.o00 = y0c * Ww + x0c; c.o01 = y0c * Ww + x1c;
    c.o10 = y1c * Ww + x0c; c.o11 = y1c * Ww + x1c;
    return c;
}

// ---------------------------------------------------------------------------
// Deformable conv + folded BN + Mish — software-pipelined block GEMM.
// 128 px/block, 288 threads, 18 stages (tap x dg), double-buffered smem.
// GEMM: 4o x 4px per thread via FFMA2; sampling interleaved between chunks.
// ---------------------------------------------------------------------------
extern __shared__ char smem_raw[];

__global__ __launch_bounds__(NT, 2) void deform_kernel(
    const float* __restrict__ x, float* __restrict__ out)
{
    float* vbuf = (float*)smem_raw;                 // [2][64][128] floats 64KB
    ull*   wbuf = (ull*)(smem_raw + 65536);         // [2][64*36] ull   36KB

    int n = blockIdx.y;
    int p0 = blockIdx.x * PB;
    int tid = threadIdx.x;
    int og = tid / 32;           // 0..8 (o-group)
    int pg = tid % 32;           // px-group

    bool samp = tid < 256;
    int sp  = tid & 127;
    int sc0 = (tid >> 7) * 32;   // 0 or 32
    int pS  = min(p0 + sp, HWO - 1);
    int ys = pS / WO, xs = pS % WO;

    const float* xb = x + (size_t)n * C1 * HW;
    const float* offp = g_offset + (size_t)n * C2 * HWO + pS;

    ull acc[8];
#pragma unroll
    for (int i = 0; i < 8; i++) acc[i] = 0ull;

    // ---- prologue: stage 0 weights + samples into buffer 0
    {
        const float4* gw = (const float4*)g_wt2;
        float4* wd = (float4*)wbuf;
#pragma unroll
        for (int i = 0; i < 4; i++) wd[tid + i * 288] = gw[tid + i * 288];
    }
    Ctx ctxS;
    if (samp) {
        float dy = offp[0];
        float dx = offp[HWO];
        ctxS = make_ctx(ys, xs, 0, 0, dy, dx);
        const float* pc = xb + sc0 * HW;
        float* vd = vbuf + sc0 * PB + sp;
        for (int cb = 0; cb < 32; cb += 4) {
            float g00[4], g01[4], g10[4], g11[4];
#pragma unroll
            for (int i = 0; i < 4; i++) {
                const float* pp = pc + (cb + i) * HW;
                g00[i] = __ldg(pp + ctxS.o00); g01[i] = __ldg(pp + ctxS.o01);
                g10[i] = __ldg(pp + ctxS.o10); g11[i] = __ldg(pp + ctxS.o11);
            }
#pragma unroll
            for (int i = 0; i < 4; i++) {
                float v = fmaf(ctxS.W00, g00[i], fmaf(ctxS.W01, g01[i],
                          fmaf(ctxS.W10, g10[i], ctxS.W11 * g11[i])));
                vd[(cb + i) * PB] = v;
            }
        }
    }
    __syncthreads();

    // ---- 18 stages
    for (int s = 0; s < 18; s++) {
        int cur = s & 1, nxt = cur ^ 1;
        const float* vc = vbuf + cur * 8192;
        const ull*   wc = wbuf + cur * 2304;
        bool hasNext = (s < 17);

        // prefetch next-stage weights to registers
        float4 wr0, wr1, wr2, wr3;
        if (hasNext) {
            const float4* gw = (const float4*)(g_wt2 + (size_t)(s + 1) * 2304);
            wr0 = gw[tid]; wr1 = gw[tid + 288];
            wr2 = gw[tid + 576]; wr3 = gw[tid + 864];
        }

        // issue next-stage offset loads (ctx computed after first GEMM chunk)
        float dyR = 0.f, dxR = 0.f;
        int t1i = 0, t1j = 0, dg1 = 0;
        if (hasNext && samp) {
            int s1 = s + 1;
            int t1 = s1 >> 1; dg1 = s1 & 1;
            t1i = t1 / 3; t1j = t1 % 3;
            dyR = offp[(dg1 * 18 + t1 * 2) * HWO];
            dxR = offp[(dg1 * 18 + t1 * 2 + 1) * HWO];
        }
        const float* pcN = xb + (dg1 * 64 + sc0) * HW;
        float* vdN = vbuf + nxt * 8192 + sc0 * PB + sp;

        float g00[4], g01[4], g10[4], g11[4];

        for (int kb = 0; kb < 8; kb++) {
            // GEMM chunk: 8 channels
#pragma unroll
            for (int cc = 0; cc < 8; cc++) {
                int c = kb * 8 + cc;
                ulonglong2 vv  = *(const ulonglong2*)(vc + c * PB + pg * 4);
                const ull* wp = wc + c * 36 + og * 4;
                ulonglong2 w01 = *(const ulonglong2*)(wp);
                ulonglong2 w23 = *(const ulonglong2*)(wp + 2);
                acc[0] = fma2(w01.x, vv.x, acc[0]);
                acc[1] = fma2(w01.x, vv.y, acc[1]);
                acc[2] = fma2(w01.y, vv.x, acc[2]);
                acc[3] = fma2(w01.y, vv.y, acc[3]);
                acc[4] = fma2(w23.x, vv.x, acc[4]);
                acc[5] = fma2(w23.x, vv.y, acc[5]);
                acc[6] = fma2(w23.y, vv.x, acc[6]);
                acc[7] = fma2(w23.y, vv.y, acc[7]);
            }
            // sampling interleave for next stage
            if (hasNext && samp) {
                if (kb == 0) {
                    ctxS = make_ctx(ys, xs, t1i, t1j, dyR, dxR);
                } else {
                    int cb = (kb - 1) * 4;
#pragma unroll
                    for (int i = 0; i < 4; i++) {
                        float v = fmaf(ctxS.W00, g00[i], fmaf(ctxS.W01, g01[i],
                                  fmaf(ctxS.W10, g10[i], ctxS.W11 * g11[i])));
                        vdN[(cb + i) * PB] = v;
                    }
                }
                int cb = kb * 4;
#pragma unroll
                for (int i = 0; i < 4; i++) {
                    const float* pp = pcN + (cb + i) * HW;
                    g00[i] = __ldg(pp + ctxS.o00); g01[i] = __ldg(pp + ctxS.o01);
                    g10[i] = __ldg(pp + ctxS.o10); g11[i] = __ldg(pp + ctxS.o11);
                }
            }
        }

        if (hasNext) {
            if (samp) {
                int cb = 28;
#pragma unroll
                for (int i = 0; i < 4; i++) {
                    float v = fmaf(ctxS.W00, g00[i], fmaf(ctxS.W01, g01[i],
                              fmaf(ctxS.W10, g10[i], ctxS.W11 * g11[i])));
                    vdN[(cb + i) * PB] = v;
                }
            }
            float4* wd = (float4*)(wbuf + nxt * 2304);
            wd[tid] = wr0; wd[tid + 288] = wr1;
            wd[tid + 576] = wr2; wd[tid + 864] = wr3;
        }
        __syncthreads();
    }

    // ---- epilogue: bias + Mish
    int pxb = p0 + pg * 4;
#pragma unroll
    for (int i = 0; i < 4; i++) {
        int o = og * 4 + i;
        float b = __ldg(g_bias + o);
        float z[4];
        z[0] = lo2(acc[i * 2 + 0]) + b;
        z[1] = hi2(acc[i * 2 + 0]) + b;
        z[2] = lo2(acc[i * 2 + 1]) + b;
        z[3] = hi2(acc[i * 2 + 1]) + b;
        float r[4];
#pragma unroll
        for (int j = 0; j < 4; j++) {
            float sp2 = (z[j] > 20.f) ? z[j] : log1pf(expf(z[j]));
            r[j] = z[j] * tanhf(sp2);
        }
        float* ob = out + ((size_t)n * C2 + o) * HWO + pxb;
        if (pxb + 3 < HWO) {
            *(float4*)ob = make_float4(r[0], r[1], r[2], r[3]);
        } else {
#pragma unroll
            for (int j = 0; j < 4; j++)
                if (pxb + j < HWO) ob[j] = r[j];
        }
    }
}

// ---------------------------------------------------------------------------
extern "C" void kernel_launch(void* const* d_in, const int* in_sizes, int n_in,
                              void* d_out, int out_size)
{
    const float* x        = (const float*)d_in[0];
    const float* conv_w   = (const float*)d_in[1];
    const float* deform_w = (const float*)d_in[2];
    const float* bn_gamma = (const float*)d_in[3];
    const float* bn_beta  = (const float*)d_in[4];
    const float* bn_mean  = (const float*)d_in[5];
    const float* bn_var   = (const float*)d_in[6];
    float* out = (float*)d_out;

    cudaFuncSetAttribute(deform_kernel,
                         cudaFuncAttributeMaxDynamicSharedMemorySize, 102400);

    prep_kernel<<<(9 * C1 * C2 + 255) / 256, 256>>>(
        deform_w, bn_gamma, bn_beta, bn_mean, bn_var);

    offset_conv_kernel<<<dim3(6, 32, 16), 192>>>(x, conv_w);

    deform_kernel<<<dim3((HWO + PB - 1) / PB, NN), NT, 102400>>>(x, out);
}

// round 8
// speedup vs baseline: 1.2248x; 1.2248x over previous
#include <cuda_runtime.h>
#include <cuda_fp16.h>
#include <math.h>

#define NN 4
#define C1 128
#define C2 36
#define Hh 192
#define Ww 192
#define HO 190
#define WO 190
#define HW (Hh*Ww)
#define HWO (HO*WO)

typedef unsigned long long ull;

// Scratch (device globals: allocation-free rule)
__device__ float g_offset[NN*C2*HWO];   // offset conv output [N,36,HO,WO]
__device__ float g_wt[9*C1*C2];         // deform_w [tap][c][o], BN-scaled
__device__ float g_bias[C2];            // folded BN bias
__device__ uint2 g_xh[(size_t)NN*32*HW];// x as fp16, 4ch packed: [n][cg=32][h][w]

// ---- packed f32x2 helpers -------------------------------------------------
__device__ __forceinline__ ull fma2(ull a, ull b, ull c) {
    ull d; asm("fma.rn.f32x2 %0,%1,%2,%3;" : "=l"(d) : "l"(a), "l"(b), "l"(c));
    return d;
}
__device__ __forceinline__ ull pack2(float x, float y) {
    ull d; asm("mov.b64 %0,{%1,%2};" : "=l"(d) : "f"(x), "f"(y));
    return d;
}
__device__ __forceinline__ float lo2(ull a) { return __uint_as_float((unsigned)a); }
__device__ __forceinline__ float hi2(ull a) { return __uint_as_float((unsigned)(a >> 32)); }

// ---------------------------------------------------------------------------
// Prep: transpose deform_w [o][c][3][3] -> g_wt[tap][c][o], folding BN scale.
// ---------------------------------------------------------------------------
__global__ void prep_kernel(const float* __restrict__ dw,
                            const float* __restrict__ gamma,
                            const float* __restrict__ beta,
                            const float* __restrict__ mean,
                            const float* __restrict__ var)
{
    int idx = blockIdx.x * 256 + threadIdx.x;
    if (idx < 9 * C1 * C2) {
        int t = idx / (C1 * C2);
        int r = idx % (C1 * C2);
        int c = r / C2, o = r % C2;
        float s = gamma[o] * rsqrtf(var[o] + 1e-5f);
        g_wt[idx] = dw[(o * C1 + c) * 9 + t] * s;
    }
    if (idx < C2) {
        float s = gamma[idx] * rsqrtf(var[idx] + 1e-5f);
        g_bias[idx] = beta[idx] - mean[idx] * s;
    }
}

// ---------------------------------------------------------------------------
// Pack x [N,C,H,W] fp32 -> g_xh [N][cg][H,W] fp16, 4 channels per uint2.
// ---------------------------------------------------------------------------
__global__ __launch_bounds__(256) void pack_kernel(const float* __restrict__ x)
{
    int idx = blockIdx.x * 256 + threadIdx.x;   // pixel within HW
    int cg  = blockIdx.y;                        // channel group 0..31
    int n   = blockIdx.z;

    const float* xb = x + ((size_t)n * C1 + cg * 4) * HW + idx;
    __half h0 = __float2half_rn(xb[0]);
    __half h1 = __float2half_rn(xb[HW]);
    __half h2 = __float2half_rn(xb[2 * HW]);
    __half h3 = __float2half_rn(xb[3 * HW]);

    uint2 w;
    w.x = ((unsigned)__half_as_ushort(h1) << 16) | (unsigned)__half_as_ushort(h0);
    w.y = ((unsigned)__half_as_ushort(h3) << 16) | (unsigned)__half_as_ushort(h2);
    g_xh[((size_t)n * 32 + cg) * HW + idx] = w;
}

// ---------------------------------------------------------------------------
// Offset-generating grouped conv (groups=4, VALID, 3x3) — known-good version.
// ---------------------------------------------------------------------------
__global__ __launch_bounds__(192) void offset_conv_kernel(
    const float* __restrict__ x, const float* __restrict__ cw)
{
    __shared__ float sx[32 * 8 * 34];
    __shared__ float ws[32 * 9 * 9];

    int n = blockIdx.z >> 2;
    int g = blockIdx.z & 3;
    int x0 = blockIdx.x * 32;
    int y0 = blockIdx.y * 6;
    int tid = threadIdx.x;

    for (int idx = tid; idx < 2592; idx += 192) {
        int o = idx % 9; int rem = idx / 9;
        int tap = rem % 9; int ci = rem / 9;
        ws[idx] = cw[((g * 9 + o) * 32 + ci) * 9 + tap];
    }

    const float* xb = x + ((size_t)n * C1 + g * 32) * HW;
    for (int idx = tid; idx < 32 * 8 * 34; idx += 192) {
        int ci = idx / 272;
        int r  = (idx % 272) / 34;
        int col = idx % 34;
        int gy = y0 + r, gx = x0 + col;
        float v = 0.f;
        if (gy < Hh && gx < Ww) v = xb[ci * HW + gy * Ww + gx];
        sx[idx] = v;
    }
    __syncthreads();

    int lx = tid & 31, ly = tid >> 5;
    float acc[9];
#pragma unroll
    for (int o = 0; o < 9; o++) acc[o] = 0.f;

    for (int ci = 0; ci < 32; ci++) {
        int base = ci * 272 + ly * 34 + lx;
#pragma unroll
        for (int tap = 0; tap < 9; tap++) {
            int i = tap / 3, j = tap % 3;
            float v = sx[base + i * 34 + j];
            const float* wp = &ws[(ci * 9 + tap) * 9];
#pragma unroll
            for (int o = 0; o < 9; o++) acc[o] = fmaf(v, wp[o], acc[o]);
        }
    }

    int yy = y0 + ly, xx = x0 + lx;
    if (yy < HO && xx < WO) {
        float* op = g_offset + ((size_t)n * C2 + g * 9) * HWO + yy * WO + xx;
#pragma unroll
        for (int o = 0; o < 9; o++) op[o * HWO] = acc[o];
    }
}

// ---------------------------------------------------------------------------
struct Ctx {
    int o00, o01, o10, o11;
    float W00, W01, W10, W11;
};

__device__ __forceinline__ Ctx make_ctx(int yy, int xx, int i, int j,
                                        float dy, float dx)
{
    Ctx c;
    float py = (float)(yy + i) + dy;
    float px = (float)(xx + j) + dx;
    float fy0 = floorf(py), fx0 = floorf(px);
    float wy1 = py - fy0, wx1 = px - fx0;
    float wy0 = 1.f - wy1, wx0 = 1.f - wx1;

    bool vy0 = (fy0       >= 0.f) && (fy0       <= (float)(Hh - 1));
    bool vy1 = (fy0 + 1.f >= 0.f) && (fy0 + 1.f <= (float)(Hh - 1));
    bool vx0 = (fx0       >= 0.f) && (fx0       <= (float)(Ww - 1));
    bool vx1 = (fx0 + 1.f >= 0.f) && (fx0 + 1.f <= (float)(Ww - 1));

    int y0i = (int)fy0, x0i = (int)fx0;
    int y0c = min(max(y0i,     0), Hh - 1);
    int y1c = min(max(y0i + 1, 0), Hh - 1);
    int x0c = min(max(x0i,     0), Ww - 1);
    int x1c = min(max(x0i + 1, 0), Ww - 1);

    c.W00 = wy0 * wx0 * ((vy0 && vx0) ? 1.f : 0.f);
    c.W01 = wy0 * wx1 * ((vy0 && vx1) ? 1.f : 0.f);
    c.W10 = wy1 * wx0 * ((vy1 && vx0) ? 1.f : 0.f);
    c.W11 = wy1 * wx1 * ((vy1 && vx1) ? 1.f : 0.f);

    c.o00 = y0c * Ww + x0c; c.o01 = y0c * Ww + x1c;
    c.o10 = y1c * Ww + x0c; c.o11 = y1c * Ww + x1c;
    return c;
}

// 4-channel bilinear from packed fp16 corners (fp32 math after conversion)
__device__ __forceinline__ void bilin4(const Ctx& C, uint2 q00, uint2 q01,
                                       uint2 q10, uint2 q11, float v[4])
{
    float2 f00a = __half22float2(*(__half2*)&q00.x);
    float2 f00b = __half22float2(*(__half2*)&q00.y);
    float2 f01a = __half22float2(*(__half2*)&q01.x);
    float2 f01b = __half22float2(*(__half2*)&q01.y);
    float2 f10a = __half22float2(*(__half2*)&q10.x);
    float2 f10b = __half22float2(*(__half2*)&q10.y);
    float2 f11a = __half22float2(*(__half2*)&q11.x);
    float2 f11b = __half22float2(*(__half2*)&q11.y);
    v[0] = fmaf(C.W00, f00a.x, fmaf(C.W01, f01a.x, fmaf(C.W10, f10a.x, C.W11 * f11a.x)));
    v[1] = fmaf(C.W00, f00a.y, fmaf(C.W01, f01a.y, fmaf(C.W10, f10a.y, C.W11 * f11a.y)));
    v[2] = fmaf(C.W00, f00b.x, fmaf(C.W01, f01b.x, fmaf(C.W10, f10b.x, C.W11 * f11b.x)));
    v[3] = fmaf(C.W00, f00b.y, fmaf(C.W01, f01b.y, fmaf(C.W10, f10b.y, C.W11 * f11b.y)));
}

// ---------------------------------------------------------------------------
// Deformable conv + folded BN + Mish. One thread per output pixel.
// Gathers: LDG.64 of 4 packed fp16 channels. FFMA2 GEMM vs broadcast smem
// weights; 18 packed f32x2 accumulators.
// ---------------------------------------------------------------------------
__global__ __launch_bounds__(128, 4) void deform_kernel(float* __restrict__ out)
{
    __shared__ float wts[C1 * C2];   // per-tap weights [c=128][o=36] = 18KB

    int n = blockIdx.y;
    int p = blockIdx.x * 128 + threadIdx.x;
    bool active = (p < HWO);
    if (!active) p = HWO - 1;
    int yy = p / WO, xx = p % WO;

    const uint2* xh = g_xh + (size_t)n * 32 * HW;
    const float* offb = g_offset + (size_t)n * C2 * HWO + yy * WO + xx;
    const float4* gwt4 = (const float4*)g_wt;

    ull acc[18];
#pragma unroll
    for (int j = 0; j < 18; j++) acc[j] = 0ull;

    for (int t = 0; t < 9; t++) {
        __syncthreads();
        {
            float4* wd = (float4*)wts;
            const float4* gw = gwt4 + t * 1152;
#pragma unroll
            for (int i = 0; i < 9; i++)
                wd[threadIdx.x + i * 128] = gw[threadIdx.x + i * 128];
        }
        __syncthreads();

        int ti = t / 3, tj = t % 3;
        float dy0 = offb[(t * 2     ) * HWO];
        float dx0 = offb[(t * 2 + 1 ) * HWO];
        float dy1 = offb[(18 + t * 2) * HWO];
        float dx1 = offb[(19 + t * 2) * HWO];
        Ctx A = make_ctx(yy, xx, ti, tj, dy0, dx0);
        Ctx B = make_ctx(yy, xx, ti, tj, dy1, dx1);

        const ulonglong2* w0 = (const ulonglong2*)wts;             // dg0 [c][36]
        const ulonglong2* w1 = (const ulonglong2*)(wts + 64 * C2); // dg1

#pragma unroll 2
        for (int cg = 0; cg < 16; cg++) {
            const uint2* p0 = xh + (size_t)cg * HW;         // dg0: ch 4cg..4cg+3
            const uint2* p1 = xh + (size_t)(16 + cg) * HW;  // dg1
            uint2 a00 = __ldg(p0 + A.o00), a01 = __ldg(p0 + A.o01);
            uint2 a10 = __ldg(p0 + A.o10), a11 = __ldg(p0 + A.o11);
            uint2 b00 = __ldg(p1 + B.o00), b01 = __ldg(p1 + B.o01);
            uint2 b10 = __ldg(p1 + B.o10), b11 = __ldg(p1 + B.o11);

            float va[4], vb[4];
            bilin4(A, a00, a01, a10, a11, va);
            bilin4(B, b00, b01, b10, b11, vb);

#pragma unroll
            for (int k = 0; k < 4; k++) {
                int c0 = cg * 4 + k;
                ull vv0 = pack2(va[k], va[k]);
                ull vv1 = pack2(vb[k], vb[k]);
                const ulonglong2* wp0 = w0 + c0 * 9;
                const ulonglong2* wp1 = w1 + c0 * 9;
#pragma unroll
                for (int q = 0; q < 9; q++) {
                    ulonglong2 ww0 = wp0[q];
                    ulonglong2 ww1 = wp1[q];
                    acc[2 * q]     = fma2(vv0, ww0.x, acc[2 * q]);
                    acc[2 * q + 1] = fma2(vv0, ww0.y, acc[2 * q + 1]);
                    acc[2 * q]     = fma2(vv1, ww1.x, acc[2 * q]);
                    acc[2 * q + 1] = fma2(vv1, ww1.y, acc[2 * q + 1]);
                }
            }
        }
    }

    if (active) {
        float* ob = out + (size_t)n * C2 * HWO + yy * WO + xx;
#pragma unroll
        for (int pr = 0; pr < 18; pr++) {
            int o0 = 2 * pr;
            float z0 = lo2(acc[pr]) + __ldg(g_bias + o0);
            float z1 = hi2(acc[pr]) + __ldg(g_bias + o0 + 1);
            float sp0 = (z0 > 20.f) ? z0 : log1pf(expf(z0));
            float sp1 = (z1 > 20.f) ? z1 : log1pf(expf(z1));
            ob[(size_t)o0 * HWO]       = z0 * tanhf(sp0);
            ob[(size_t)(o0 + 1) * HWO] = z1 * tanhf(sp1);
        }
    }
}

// ---------------------------------------------------------------------------
extern "C" void kernel_launch(void* const* d_in, const int* in_sizes, int n_in,
                              void* d_out, int out_size)
{
    const float* x        = (const float*)d_in[0];
    const float* conv_w   = (const float*)d_in[1];
    const float* deform_w = (const float*)d_in[2];
    const float* bn_gamma = (const float*)d_in[3];
    const float* bn_beta  = (const float*)d_in[4];
    const float* bn_mean  = (const float*)d_in[5];
    const float* bn_var   = (const float*)d_in[6];
    float* out = (float*)d_out;

    prep_kernel<<<(9 * C1 * C2 + 255) / 256, 256>>>(
        deform_w, bn_gamma, bn_beta, bn_mean, bn_var);

    pack_kernel<<<dim3(HW / 256, 32, NN), 256>>>(x);

    offset_conv_kernel<<<dim3(6, 32, 16), 192>>>(x, conv_w);

    deform_kernel<<<dim3((HWO + 127) / 128, NN), 128>>>(out);
}

// round 9
// speedup vs baseline: 1.5540x; 1.2688x over previous
#include <cuda_runtime.h>
#include <cuda_fp16.h>
#include <math.h>

#define NN 4
#define C1 128
#define C2 36
#define Hh 192
#define Ww 192
#define HO 190
#define WO 190
#define HW (Hh*Ww)
#define HWO (HO*WO)

typedef unsigned long long ull;

// Scratch (device globals: allocation-free rule)
__device__ float g_offset[NN*C2*HWO];   // offset conv output [N,36,HO,WO]
__device__ float g_wt[9*C1*C2];         // deform_w [tap][c][o], BN-scaled
__device__ float g_bias[C2];            // folded BN bias
__device__ uint2 g_xh[(size_t)NN*32*HW];// x as fp16, 4ch packed: [n][cg=32][h][w]

// ---- packed f32x2 helpers -------------------------------------------------
__device__ __forceinline__ ull fma2(ull a, ull b, ull c) {
    ull d; asm("fma.rn.f32x2 %0,%1,%2,%3;" : "=l"(d) : "l"(a), "l"(b), "l"(c));
    return d;
}
__device__ __forceinline__ ull pack2(float x, float y) {
    ull d; asm("mov.b64 %0,{%1,%2};" : "=l"(d) : "f"(x), "f"(y));
    return d;
}
__device__ __forceinline__ float lo2(ull a) { return __uint_as_float((unsigned)a); }
__device__ __forceinline__ float hi2(ull a) { return __uint_as_float((unsigned)(a >> 32)); }

// ---------------------------------------------------------------------------
// Prep: transpose deform_w [o][c][3][3] -> g_wt[tap][c][o], folding BN scale.
// ---------------------------------------------------------------------------
__global__ void prep_kernel(const float* __restrict__ dw,
                            const float* __restrict__ gamma,
                            const float* __restrict__ beta,
                            const float* __restrict__ mean,
                            const float* __restrict__ var)
{
    int idx = blockIdx.x * 256 + threadIdx.x;
    if (idx < 9 * C1 * C2) {
        int t = idx / (C1 * C2);
        int r = idx % (C1 * C2);
        int c = r / C2, o = r % C2;
        float s = gamma[o] * rsqrtf(var[o] + 1e-5f);
        g_wt[idx] = dw[(o * C1 + c) * 9 + t] * s;
    }
    if (idx < C2) {
        float s = gamma[idx] * rsqrtf(var[idx] + 1e-5f);
        g_bias[idx] = beta[idx] - mean[idx] * s;
    }
}

// ---------------------------------------------------------------------------
// Pack x [N,C,H,W] fp32 -> g_xh [N][cg][H,W] fp16, 4 channels per uint2.
// ---------------------------------------------------------------------------
__global__ __launch_bounds__(256) void pack_kernel(const float* __restrict__ x)
{
    int idx = blockIdx.x * 256 + threadIdx.x;
    int cg  = blockIdx.y;
    int n   = blockIdx.z;

    const float* xb = x + ((size_t)n * C1 + cg * 4) * HW + idx;
    __half h0 = __float2half_rn(xb[0]);
    __half h1 = __float2half_rn(xb[HW]);
    __half h2 = __float2half_rn(xb[2 * HW]);
    __half h3 = __float2half_rn(xb[3 * HW]);

    uint2 w;
    w.x = ((unsigned)__half_as_ushort(h1) << 16) | (unsigned)__half_as_ushort(h0);
    w.y = ((unsigned)__half_as_ushort(h3) << 16) | (unsigned)__half_as_ushort(h2);
    g_xh[((size_t)n * 32 + cg) * HW + idx] = w;
}

// ---------------------------------------------------------------------------
// Offset-generating grouped conv (groups=4, VALID, 3x3, stride 1)
// 32x12 output tile, 2 rows/thread, float4-padded weights (5 LDS / 18 FMA).
// ---------------------------------------------------------------------------
__global__ __launch_bounds__(192) void offset_conv_kernel(
    const float* __restrict__ x, const float* __restrict__ cw)
{
    __shared__ float  sx[16 * 14 * 34];   // 16-ch chunk, 14 rows, 34 cols
    __shared__ float4 wsv[32 * 9 * 3];    // [ci][tap][12 floats padded]

    int n = blockIdx.z >> 2;
    int g = blockIdx.z & 3;
    int x0 = blockIdx.x * 32;
    int y0 = blockIdx.y * 12;
    int tid = threadIdx.x;

    float* wsf = (float*)wsv;
    for (int idx = tid; idx < 32 * 9 * 12; idx += 192) {
        int o = idx % 12; int rem = idx / 12;
        int tap = rem % 9; int ci = rem / 9;
        wsf[idx] = (o < 9) ? cw[((g * 9 + o) * 32 + ci) * 9 + tap] : 0.f;
    }

    int lx = tid & 31, ly = tid >> 5;
    float acc[18];
#pragma unroll
    for (int o = 0; o < 18; o++) acc[o] = 0.f;

    for (int chunk = 0; chunk < 2; chunk++) {
        __syncthreads();
        const float* xb = x + ((size_t)n * C1 + g * 32 + chunk * 16) * HW;
        for (int idx = tid; idx < 16 * 14 * 34; idx += 192) {
            int ci = idx / 476;
            int r  = (idx % 476) / 34;
            int col = idx % 34;
            int gy = y0 + r, gx = x0 + col;
            float v = 0.f;
            if (gy < Hh && gx < Ww) v = xb[ci * HW + gy * Ww + gx];
            sx[idx] = v;
        }
        __syncthreads();

        for (int ci = 0; ci < 16; ci++) {
            int base = ci * 476 + ly * 34 + lx;
            const float4* wp = wsv + ((chunk * 16 + ci) * 9) * 3;
#pragma unroll
            for (int tap = 0; tap < 9; tap++) {
                int i = tap / 3, j = tap % 3;
                float va = sx[base + i * 34 + j];
                float vb = sx[base + (i + 6) * 34 + j];
                float4 w0 = wp[tap * 3 + 0];
                float4 w1 = wp[tap * 3 + 1];
                float4 w2 = wp[tap * 3 + 2];
                acc[0] = fmaf(va, w0.x, acc[0]);
                acc[1] = fmaf(va, w0.y, acc[1]);
                acc[2] = fmaf(va, w0.z, acc[2]);
                acc[3] = fmaf(va, w0.w, acc[3]);
                acc[4] = fmaf(va, w1.x, acc[4]);
                acc[5] = fmaf(va, w1.y, acc[5]);
                acc[6] = fmaf(va, w1.z, acc[6]);
                acc[7] = fmaf(va, w1.w, acc[7]);
                acc[8] = fmaf(va, w2.x, acc[8]);
                acc[9]  = fmaf(vb, w0.x, acc[9]);
                acc[10] = fmaf(vb, w0.y, acc[10]);
                acc[11] = fmaf(vb, w0.z, acc[11]);
                acc[12] = fmaf(vb, w0.w, acc[12]);
                acc[13] = fmaf(vb, w1.x, acc[13]);
                acc[14] = fmaf(vb, w1.y, acc[14]);
                acc[15] = fmaf(vb, w1.z, acc[15]);
                acc[16] = fmaf(vb, w1.w, acc[16]);
                acc[17] = fmaf(vb, w2.x, acc[17]);
            }
        }
    }

    int xx = x0 + lx;
    int ya = y0 + ly;
    int yb = y0 + ly + 6;
    if (xx < WO) {
        float* op = g_offset + ((size_t)n * C2 + g * 9) * HWO;
#pragma unroll
        for (int o = 0; o < 9; o++)
            op[o * HWO + ya * WO + xx] = acc[o];
        if (yb < HO) {
#pragma unroll
            for (int o = 0; o < 9; o++)
                op[o * HWO + yb * WO + xx] = acc[9 + o];
        }
    }
}

// ---------------------------------------------------------------------------
struct Ctx {
    int o00, o01, o10, o11;
    float W00, W01, W10, W11;
};

__device__ __forceinline__ Ctx make_ctx(int yy, int xx, int i, int j,
                                        float dy, float dx)
{
    Ctx c;
    float py = (float)(yy + i) + dy;
    float px = (float)(xx + j) + dx;
    float fy0 = floorf(py), fx0 = floorf(px);
    float wy1 = py - fy0, wx1 = px - fx0;
    float wy0 = 1.f - wy1, wx0 = 1.f - wx1;

    bool vy0 = (fy0       >= 0.f) && (fy0       <= (float)(Hh - 1));
    bool vy1 = (fy0 + 1.f >= 0.f) && (fy0 + 1.f <= (float)(Hh - 1));
    bool vx0 = (fx0       >= 0.f) && (fx0       <= (float)(Ww - 1));
    bool vx1 = (fx0 + 1.f >= 0.f) && (fx0 + 1.f <= (float)(Ww - 1));

    int y0i = (int)fy0, x0i = (int)fx0;
    int y0c = min(max(y0i,     0), Hh - 1);
    int y1c = min(max(y0i + 1, 0), Hh - 1);
    int x0c = min(max(x0i,     0), Ww - 1);
    int x1c = min(max(x0i + 1, 0), Ww - 1);

    c.W00 = wy0 * wx0 * ((vy0 && vx0) ? 1.f : 0.f);
    c.W01 = wy0 * wx1 * ((vy0 && vx1) ? 1.f : 0.f);
    c.W10 = wy1 * wx0 * ((vy1 && vx0) ? 1.f : 0.f);
    c.W11 = wy1 * wx1 * ((vy1 && vx1) ? 1.f : 0.f);

    c.o00 = y0c * Ww + x0c; c.o01 = y0c * Ww + x1c;
    c.o10 = y1c * Ww + x0c; c.o11 = y1c * Ww + x1c;
    return c;
}

__device__ __forceinline__ void bilin4(const Ctx& C, uint2 q00, uint2 q01,
                                       uint2 q10, uint2 q11, float v[4])
{
    float2 f00a = __half22float2(*(__half2*)&q00.x);
    float2 f00b = __half22float2(*(__half2*)&q00.y);
    float2 f01a = __half22float2(*(__half2*)&q01.x);
    float2 f01b = __half22float2(*(__half2*)&q01.y);
    float2 f10a = __half22float2(*(__half2*)&q10.x);
    float2 f10b = __half22float2(*(__half2*)&q10.y);
    float2 f11a = __half22float2(*(__half2*)&q11.x);
    float2 f11b = __half22float2(*(__half2*)&q11.y);
    v[0] = fmaf(C.W00, f00a.x, fmaf(C.W01, f01a.x, fmaf(C.W10, f10a.x, C.W11 * f11a.x)));
    v[1] = fmaf(C.W00, f00a.y, fmaf(C.W01, f01a.y, fmaf(C.W10, f10a.y, C.W11 * f11a.y)));
    v[2] = fmaf(C.W00, f00b.x, fmaf(C.W01, f01b.x, fmaf(C.W10, f10b.x, C.W11 * f11b.x)));
    v[3] = fmaf(C.W00, f00b.y, fmaf(C.W01, f01b.y, fmaf(C.W10, f10b.y, C.W11 * f11b.y)));
}

// ---------------------------------------------------------------------------
// Deformable conv + folded BN + Mish. TWO pixels per thread (px, px+128):
// each weight ulonglong2 LDS feeds 4 fma2 (register reuse across pixels).
// Gathers: LDG.64 of 4 packed fp16 channels, fp32 bilinear.
// ---------------------------------------------------------------------------
__global__ __launch_bounds__(128, 3) void deform_kernel(float* __restrict__ out)
{
    __shared__ float wts[C1 * C2];   // per-tap weights [c=128][o=36] = 18KB

    int n = blockIdx.y;
    int tid = threadIdx.x;
    int p0 = blockIdx.x * 256 + tid;
    int p1 = p0 + 128;
    bool act0 = (p0 < HWO), act1 = (p1 < HWO);
    int pc0 = act0 ? p0 : (HWO - 1);
    int pc1 = act1 ? p1 : (HWO - 1);
    int y0 = pc0 / WO, x0 = pc0 % WO;
    int y1 = pc1 / WO, x1 = pc1 % WO;

    const uint2* xh = g_xh + (size_t)n * 32 * HW;
    const float* off0 = g_offset + (size_t)n * C2 * HWO + pc0;
    const float* off1 = g_offset + (size_t)n * C2 * HWO + pc1;
    const float4* gwt4 = (const float4*)g_wt;

    ull acc0[18], acc1[18];
#pragma unroll
    for (int j = 0; j < 18; j++) { acc0[j] = 0ull; acc1[j] = 0ull; }

    for (int t = 0; t < 9; t++) {
        __syncthreads();
        {
            float4* wd = (float4*)wts;
            const float4* gw = gwt4 + t * 1152;
#pragma unroll
            for (int i = 0; i < 9; i++)
                wd[tid + i * 128] = gw[tid + i * 128];
        }
        __syncthreads();

        int ti = t / 3, tj = t % 3;

#pragma unroll
        for (int dg = 0; dg < 2; dg++) {
            float dyA = off0[(dg * 18 + t * 2    ) * HWO];
            float dxA = off0[(dg * 18 + t * 2 + 1) * HWO];
            float dyB = off1[(dg * 18 + t * 2    ) * HWO];
            float dxB = off1[(dg * 18 + t * 2 + 1) * HWO];
            Ctx A = make_ctx(y0, x0, ti, tj, dyA, dxA);
            Ctx B = make_ctx(y1, x1, ti, tj, dyB, dxB);

            const ulonglong2* wdg = (const ulonglong2*)(wts + dg * 64 * C2);

#pragma unroll 2
            for (int cg = 0; cg < 16; cg++) {
                const uint2* pc = xh + (size_t)(dg * 16 + cg) * HW;
                uint2 a00 = __ldg(pc + A.o00), a01 = __ldg(pc + A.o01);
                uint2 a10 = __ldg(pc + A.o10), a11 = __ldg(pc + A.o11);
                uint2 b00 = __ldg(pc + B.o00), b01 = __ldg(pc + B.o01);
                uint2 b10 = __ldg(pc + B.o10), b11 = __ldg(pc + B.o11);

                float va[4], vb[4];
                bilin4(A, a00, a01, a10, a11, va);
                bilin4(B, b00, b01, b10, b11, vb);

#pragma unroll
                for (int k = 0; k < 4; k++) {
                    ull vv0 = pack2(va[k], va[k]);
                    ull vv1 = pack2(vb[k], vb[k]);
                    const ulonglong2* wp = wdg + (cg * 4 + k) * 9;
#pragma unroll
                    for (int q = 0; q < 9; q++) {
                        ulonglong2 ww = wp[q];
                        acc0[2 * q]     = fma2(vv0, ww.x, acc0[2 * q]);
                        acc0[2 * q + 1] = fma2(vv0, ww.y, acc0[2 * q + 1]);
                        acc1[2 * q]     = fma2(vv1, ww.x, acc1[2 * q]);
                        acc1[2 * q + 1] = fma2(vv1, ww.y, acc1[2 * q + 1]);
                    }
                }
            }
        }
    }

    float* ob = out + (size_t)n * C2 * HWO;
#pragma unroll
    for (int pr = 0; pr < 18; pr++) {
        int o0 = 2 * pr;
        float bz0 = __ldg(g_bias + o0);
        float bz1 = __ldg(g_bias + o0 + 1);
        if (act0) {
            float z0 = lo2(acc0[pr]) + bz0;
            float z1 = hi2(acc0[pr]) + bz1;
            float sp0 = (z0 > 20.f) ? z0 : log1pf(expf(z0));
            float sp1 = (z1 > 20.f) ? z1 : log1pf(expf(z1));
            ob[(size_t)o0 * HWO + p0]       = z0 * tanhf(sp0);
            ob[(size_t)(o0 + 1) * HWO + p0] = z1 * tanhf(sp1);
        }
        if (act1) {
            float z0 = lo2(acc1[pr]) + bz0;
            float z1 = hi2(acc1[pr]) + bz1;
            float sp0 = (z0 > 20.f) ? z0 : log1pf(expf(z0));
            float sp1 = (z1 > 20.f) ? z1 : log1pf(expf(z1));
            ob[(size_t)o0 * HWO + p1]       = z0 * tanhf(sp0);
            ob[(size_t)(o0 + 1) * HWO + p1] = z1 * tanhf(sp1);
        }
    }
}

// ---------------------------------------------------------------------------
extern "C" void kernel_launch(void* const* d_in, const int* in_sizes, int n_in,
                              void* d_out, int out_size)
{
    const float* x        = (const float*)d_in[0];
    const float* conv_w   = (const float*)d_in[1];
    const float* deform_w = (const float*)d_in[2];
    const float* bn_gamma = (const float*)d_in[3];
    const float* bn_beta  = (const float*)d_in[4];
    const float* bn_mean  = (const float*)d_in[5];
    const float* bn_var   = (const float*)d_in[6];
    float* out = (float*)d_out;

    prep_kernel<<<(9 * C1 * C2 + 255) / 256, 256>>>(
        deform_w, bn_gamma, bn_beta, bn_mean, bn_var);

    pack_kernel<<<dim3(HW / 256, 32, NN), 256>>>(x);

    offset_conv_kernel<<<dim3(6, 16, 16), 192>>>(x, conv_w);

    deform_kernel<<<dim3((HWO + 255) / 256, NN), 128>>>(out);
}

// round 10
// speedup vs baseline: 1.6624x; 1.0697x over previous
#include <cuda_runtime.h>
#include <cuda_fp16.h>
#include <math.h>

#define NN 4
#define C1 128
#define C2 36
#define Hh 192
#define Ww 192
#define HO 190
#define WO 190
#define HW (Hh*Ww)
#define HWO (HO*WO)

typedef unsigned long long ull;

// Scratch (device globals: allocation-free rule)
__device__ float g_offset[NN*C2*HWO];   // offset conv output [N,36,HO,WO]
__device__ float g_wt[9*C1*C2];         // deform_w [tap][c][o], BN-scaled
__device__ float g_bias[C2];            // folded BN bias
__device__ uint4 g_xh[(size_t)NN*16*HW];// x as fp16, 8ch packed: [n][cg=16][h][w]

// ---- packed f32x2 helpers -------------------------------------------------
__device__ __forceinline__ ull fma2(ull a, ull b, ull c) {
    ull d; asm("fma.rn.f32x2 %0,%1,%2,%3;" : "=l"(d) : "l"(a), "l"(b), "l"(c));
    return d;
}
__device__ __forceinline__ ull pack2(float x, float y) {
    ull d; asm("mov.b64 %0,{%1,%2};" : "=l"(d) : "f"(x), "f"(y));
    return d;
}
__device__ __forceinline__ float lo2(ull a) { return __uint_as_float((unsigned)a); }
__device__ __forceinline__ float hi2(ull a) { return __uint_as_float((unsigned)(a >> 32)); }

// ---------------------------------------------------------------------------
// Prep: transpose deform_w [o][c][3][3] -> g_wt[tap][c][o], folding BN scale.
// ---------------------------------------------------------------------------
__global__ void prep_kernel(const float* __restrict__ dw,
                            const float* __restrict__ gamma,
                            const float* __restrict__ beta,
                            const float* __restrict__ mean,
                            const float* __restrict__ var)
{
    int idx = blockIdx.x * 256 + threadIdx.x;
    if (idx < 9 * C1 * C2) {
        int t = idx / (C1 * C2);
        int r = idx % (C1 * C2);
        int c = r / C2, o = r % C2;
        float s = gamma[o] * rsqrtf(var[o] + 1e-5f);
        g_wt[idx] = dw[(o * C1 + c) * 9 + t] * s;
    }
    if (idx < C2) {
        float s = gamma[idx] * rsqrtf(var[idx] + 1e-5f);
        g_bias[idx] = beta[idx] - mean[idx] * s;
    }
}

// ---------------------------------------------------------------------------
// Pack x [N,C,H,W] fp32 -> g_xh [N][cg=16][H,W] fp16, 8 channels per uint4.
// ---------------------------------------------------------------------------
__global__ __launch_bounds__(256) void pack_kernel(const float* __restrict__ x)
{
    int idx = blockIdx.x * 256 + threadIdx.x;
    int cg  = blockIdx.y;     // 0..15
    int n   = blockIdx.z;

    const float* xb = x + ((size_t)n * C1 + cg * 8) * HW + idx;
    unsigned w[4];
#pragma unroll
    for (int i = 0; i < 4; i++) {
        __half lo = __float2half_rn(xb[(2 * i    ) * HW]);
        __half hi = __float2half_rn(xb[(2 * i + 1) * HW]);
        w[i] = ((unsigned)__half_as_ushort(hi) << 16) | (unsigned)__half_as_ushort(lo);
    }
    g_xh[((size_t)n * 16 + cg) * HW + idx] = make_uint4(w[0], w[1], w[2], w[3]);
}

// ---------------------------------------------------------------------------
// Offset-generating grouped conv (groups=4, VALID, 3x3, stride 1)
// 32x12 output tile, 2 rows/thread, float4-padded weights.
// ---------------------------------------------------------------------------
__global__ __launch_bounds__(192) void offset_conv_kernel(
    const float* __restrict__ x, const float* __restrict__ cw)
{
    __shared__ float  sx[16 * 14 * 34];
    __shared__ float4 wsv[32 * 9 * 3];

    int n = blockIdx.z >> 2;
    int g = blockIdx.z & 3;
    int x0 = blockIdx.x * 32;
    int y0 = blockIdx.y * 12;
    int tid = threadIdx.x;

    float* wsf = (float*)wsv;
    for (int idx = tid; idx < 32 * 9 * 12; idx += 192) {
        int o = idx % 12; int rem = idx / 12;
        int tap = rem % 9; int ci = rem / 9;
        wsf[idx] = (o < 9) ? cw[((g * 9 + o) * 32 + ci) * 9 + tap] : 0.f;
    }

    int lx = tid & 31, ly = tid >> 5;
    float acc[18];
#pragma unroll
    for (int o = 0; o < 18; o++) acc[o] = 0.f;

    for (int chunk = 0; chunk < 2; chunk++) {
        __syncthreads();
        const float* xb = x + ((size_t)n * C1 + g * 32 + chunk * 16) * HW;
        for (int idx = tid; idx < 16 * 14 * 34; idx += 192) {
            int ci = idx / 476;
            int r  = (idx % 476) / 34;
            int col = idx % 34;
            int gy = y0 + r, gx = x0 + col;
            float v = 0.f;
            if (gy < Hh && gx < Ww) v = xb[ci * HW + gy * Ww + gx];
            sx[idx] = v;
        }
        __syncthreads();

        for (int ci = 0; ci < 16; ci++) {
            int base = ci * 476 + ly * 34 + lx;
            const float4* wp = wsv + ((chunk * 16 + ci) * 9) * 3;
#pragma unroll
            for (int tap = 0; tap < 9; tap++) {
                int i = tap / 3, j = tap % 3;
                float va = sx[base + i * 34 + j];
                float vb = sx[base + (i + 6) * 34 + j];
                float4 w0 = wp[tap * 3 + 0];
                float4 w1 = wp[tap * 3 + 1];
                float4 w2 = wp[tap * 3 + 2];
                acc[0] = fmaf(va, w0.x, acc[0]);
                acc[1] = fmaf(va, w0.y, acc[1]);
                acc[2] = fmaf(va, w0.z, acc[2]);
                acc[3] = fmaf(va, w0.w, acc[3]);
                acc[4] = fmaf(va, w1.x, acc[4]);
                acc[5] = fmaf(va, w1.y, acc[5]);
                acc[6] = fmaf(va, w1.z, acc[6]);
                acc[7] = fmaf(va, w1.w, acc[7]);
                acc[8] = fmaf(va, w2.x, acc[8]);
                acc[9]  = fmaf(vb, w0.x, acc[9]);
                acc[10] = fmaf(vb, w0.y, acc[10]);
                acc[11] = fmaf(vb, w0.z, acc[11]);
                acc[12] = fmaf(vb, w0.w, acc[12]);
                acc[13] = fmaf(vb, w1.x, acc[13]);
                acc[14] = fmaf(vb, w1.y, acc[14]);
                acc[15] = fmaf(vb, w1.z, acc[15]);
                acc[16] = fmaf(vb, w1.w, acc[16]);
                acc[17] = fmaf(vb, w2.x, acc[17]);
            }
        }
    }

    int xx = x0 + lx;
    int ya = y0 + ly;
    int yb = y0 + ly + 6;
    if (xx < WO) {
        float* op = g_offset + ((size_t)n * C2 + g * 9) * HWO;
#pragma unroll
        for (int o = 0; o < 9; o++)
            op[o * HWO + ya * WO + xx] = acc[o];
        if (yb < HO) {
#pragma unroll
            for (int o = 0; o < 9; o++)
                op[o * HWO + yb * WO + xx] = acc[9 + o];
        }
    }
}

// ---------------------------------------------------------------------------
struct Ctx {
    int o00, o01, o10, o11;
    float W00, W01, W10, W11;
};

__device__ __forceinline__ Ctx make_ctx(int yy, int xx, int i, int j,
                                        float dy, float dx)
{
    Ctx c;
    float py = (float)(yy + i) + dy;
    float px = (float)(xx + j) + dx;
    float fy0 = floorf(py), fx0 = floorf(px);
    float wy1 = py - fy0, wx1 = px - fx0;
    float wy0 = 1.f - wy1, wx0 = 1.f - wx1;

    bool vy0 = (fy0       >= 0.f) && (fy0       <= (float)(Hh - 1));
    bool vy1 = (fy0 + 1.f >= 0.f) && (fy0 + 1.f <= (float)(Hh - 1));
    bool vx0 = (fx0       >= 0.f) && (fx0       <= (float)(Ww - 1));
    bool vx1 = (fx0 + 1.f >= 0.f) && (fx0 + 1.f <= (float)(Ww - 1));

    int y0i = (int)fy0, x0i = (int)fx0;
    int y0c = min(max(y0i,     0), Hh - 1);
    int y1c = min(max(y0i + 1, 0), Hh - 1);
    int x0c = min(max(x0i,     0), Ww - 1);
    int x1c = min(max(x0i + 1, 0), Ww - 1);

    c.W00 = wy0 * wx0 * ((vy0 && vx0) ? 1.f : 0.f);
    c.W01 = wy0 * wx1 * ((vy0 && vx1) ? 1.f : 0.f);
    c.W10 = wy1 * wx0 * ((vy1 && vx0) ? 1.f : 0.f);
    c.W11 = wy1 * wx1 * ((vy1 && vx1) ? 1.f : 0.f);

    c.o00 = y0c * Ww + x0c; c.o01 = y0c * Ww + x1c;
    c.o10 = y1c * Ww + x0c; c.o11 = y1c * Ww + x1c;
    return c;
}

// 8-channel bilinear from packed fp16 corners (fp32 math after conversion)
__device__ __forceinline__ void bilin8(const Ctx& C, uint4 q00, uint4 q01,
                                       uint4 q10, uint4 q11, float v[8])
{
    const unsigned* w00 = (const unsigned*)&q00;
    const unsigned* w01 = (const unsigned*)&q01;
    const unsigned* w10 = (const unsigned*)&q10;
    const unsigned* w11 = (const unsigned*)&q11;
#pragma unroll
    for (int i = 0; i < 4; i++) {
        float2 f00 = __half22float2(*(__half2*)&w00[i]);
        float2 f01 = __half22float2(*(__half2*)&w01[i]);
        float2 f10 = __half22float2(*(__half2*)&w10[i]);
        float2 f11 = __half22float2(*(__half2*)&w11[i]);
        v[2*i]   = fmaf(C.W00, f00.x, fmaf(C.W01, f01.x,
                   fmaf(C.W10, f10.x, C.W11 * f11.x)));
        v[2*i+1] = fmaf(C.W00, f00.y, fmaf(C.W01, f01.y,
                   fmaf(C.W10, f10.y, C.W11 * f11.y)));
    }
}

// ---------------------------------------------------------------------------
// Deformable conv + folded BN + Mish. TWO pixels per thread (px, px+128),
// 8 fp16 channels per LDG.128 gather, FFMA2 GEMM vs broadcast smem weights.
// ---------------------------------------------------------------------------
__global__ __launch_bounds__(128, 3) void deform_kernel(float* __restrict__ out)
{
    __shared__ float wts[C1 * C2];   // per-tap weights [c=128][o=36] = 18KB

    int n = blockIdx.y;
    int tid = threadIdx.x;
    int p0 = blockIdx.x * 256 + tid;
    int p1 = p0 + 128;
    bool act0 = (p0 < HWO), act1 = (p1 < HWO);
    int pc0 = act0 ? p0 : (HWO - 1);
    int pc1 = act1 ? p1 : (HWO - 1);
    int y0 = pc0 / WO, x0 = pc0 % WO;
    int y1 = pc1 / WO, x1 = pc1 % WO;

    const uint4* xh = g_xh + (size_t)n * 16 * HW;
    const float* off0 = g_offset + (size_t)n * C2 * HWO + pc0;
    const float* off1 = g_offset + (size_t)n * C2 * HWO + pc1;
    const float4* gwt4 = (const float4*)g_wt;

    ull acc0[18], acc1[18];
#pragma unroll
    for (int j = 0; j < 18; j++) { acc0[j] = 0ull; acc1[j] = 0ull; }

    for (int t = 0; t < 9; t++) {
        __syncthreads();
        {
            float4* wd = (float4*)wts;
            const float4* gw = gwt4 + t * 1152;
#pragma unroll
            for (int i = 0; i < 9; i++)
                wd[tid + i * 128] = gw[tid + i * 128];
        }
        __syncthreads();

        int ti = t / 3, tj = t % 3;

#pragma unroll
        for (int dg = 0; dg < 2; dg++) {
            float dyA = off0[(dg * 18 + t * 2    ) * HWO];
            float dxA = off0[(dg * 18 + t * 2 + 1) * HWO];
            float dyB = off1[(dg * 18 + t * 2    ) * HWO];
            float dxB = off1[(dg * 18 + t * 2 + 1) * HWO];
            Ctx A = make_ctx(y0, x0, ti, tj, dyA, dxA);
            Ctx B = make_ctx(y1, x1, ti, tj, dyB, dxB);

            const ulonglong2* wdg = (const ulonglong2*)(wts + dg * 64 * C2);

#pragma unroll 2
            for (int cg = 0; cg < 8; cg++) {
                const uint4* pc = xh + (size_t)(dg * 8 + cg) * HW;
                float va[8], vb[8];
                {
                    uint4 a00 = __ldg(pc + A.o00), a01 = __ldg(pc + A.o01);
                    uint4 a10 = __ldg(pc + A.o10), a11 = __ldg(pc + A.o11);
                    bilin8(A, a00, a01, a10, a11, va);
                }
                {
                    uint4 b00 = __ldg(pc + B.o00), b01 = __ldg(pc + B.o01);
                    uint4 b10 = __ldg(pc + B.o10), b11 = __ldg(pc + B.o11);
                    bilin8(B, b00, b01, b10, b11, vb);
                }

#pragma unroll
                for (int k = 0; k < 8; k++) {
                    ull vv0 = pack2(va[k], va[k]);
                    ull vv1 = pack2(vb[k], vb[k]);
                    const ulonglong2* wp = wdg + (cg * 8 + k) * 9;
#pragma unroll
                    for (int q = 0; q < 9; q++) {
                        ulonglong2 ww = wp[q];
                        acc0[2 * q]     = fma2(vv0, ww.x, acc0[2 * q]);
                        acc0[2 * q + 1] = fma2(vv0, ww.y, acc0[2 * q + 1]);
                        acc1[2 * q]     = fma2(vv1, ww.x, acc1[2 * q]);
                        acc1[2 * q + 1] = fma2(vv1, ww.y, acc1[2 * q + 1]);
                    }
                }
            }
        }
    }

    float* ob = out + (size_t)n * C2 * HWO;
#pragma unroll
    for (int pr = 0; pr < 18; pr++) {
        int o0 = 2 * pr;
        float bz0 = __ldg(g_bias + o0);
        float bz1 = __ldg(g_bias + o0 + 1);
        if (act0) {
            float z0 = lo2(acc0[pr]) + bz0;
            float z1 = hi2(acc0[pr]) + bz1;
            float sp0 = (z0 > 20.f) ? z0 : log1pf(expf(z0));
            float sp1 = (z1 > 20.f) ? z1 : log1pf(expf(z1));
            ob[(size_t)o0 * HWO + p0]       = z0 * tanhf(sp0);
            ob[(size_t)(o0 + 1) * HWO + p0] = z1 * tanhf(sp1);
        }
        if (act1) {
            float z0 = lo2(acc1[pr]) + bz0;
            float z1 = hi2(acc1[pr]) + bz1;
            float sp0 = (z0 > 20.f) ? z0 : log1pf(expf(z0));
            float sp1 = (z1 > 20.f) ? z1 : log1pf(expf(z1));
            ob[(size_t)o0 * HWO + p1]       = z0 * tanhf(sp0);
            ob[(size_t)(o0 + 1) * HWO + p1] = z1 * tanhf(sp1);
        }
    }
}

// ---------------------------------------------------------------------------
extern "C" void kernel_launch(void* const* d_in, const int* in_sizes, int n_in,
                              void* d_out, int out_size)
{
    const float* x        = (const float*)d_in[0];
    const float* conv_w   = (const float*)d_in[1];
    const float* deform_w = (const float*)d_in[2];
    const float* bn_gamma = (const float*)d_in[3];
    const float* bn_beta  = (const float*)d_in[4];
    const float* bn_mean  = (const float*)d_in[5];
    const float* bn_var   = (const float*)d_in[6];
    float* out = (float*)d_out;

    prep_kernel<<<(9 * C1 * C2 + 255) / 256, 256>>>(
        deform_w, bn_gamma, bn_beta, bn_mean, bn_var);

    pack_kernel<<<dim3(HW / 256, 16, NN), 256>>>(x);

    offset_conv_kernel<<<dim3(6, 16, 16), 192>>>(x, conv_w);

    deform_kernel<<<dim3((HWO + 255) / 256, NN), 128>>>(out);
}

// round 11
// speedup vs baseline: 2.4956x; 1.5012x over previous
#include <cuda_runtime.h>
#include <cuda_fp16.h>
#include <math.h>

#define NN 4
#define C1 128
#define C2 36
#define Hh 192
#define Ww 192
#define HO 190
#define WO 190
#define HW (Hh*Ww)
#define HWO (HO*WO)

typedef unsigned long long ull;

// Scratch (device globals: allocation-free rule)
__device__ float g_offset[NN*C2*HWO];    // offset conv output [N,36,HO,WO]
__device__ float g_bias[C2];             // folded BN bias
__device__ uint4 g_xh[(size_t)NN*16*HW]; // x fp16, 8ch packed [n][cg=16][h][w]
__device__ uint4 g_wfrag[18*12*32];      // A fragments [s=t*2+dg][mt*4+kt][lane]

// ---- packed f32x2 helpers -------------------------------------------------
__device__ __forceinline__ ull fma2(ull a, ull b, ull c) {
    ull d; asm("fma.rn.f32x2 %0,%1,%2,%3;" : "=l"(d) : "l"(a), "l"(b), "l"(c));
    return d;
}
__device__ __forceinline__ ull mul2(ull a, ull b) {
    ull d; asm("mul.rn.f32x2 %0,%1,%2;" : "=l"(d) : "l"(a), "l"(b));
    return d;
}
__device__ __forceinline__ ull pack2(float x, float y) {
    ull d; asm("mov.b64 %0,{%1,%2};" : "=l"(d) : "f"(x), "f"(y));
    return d;
}
__device__ __forceinline__ float lo2(ull a) { return __uint_as_float((unsigned)a); }
__device__ __forceinline__ float hi2(ull a) { return __uint_as_float((unsigned)(a >> 32)); }

__device__ __forceinline__ unsigned h2pack(float a, float b) {
    __half2 h = __floats2half2_rn(a, b);
    return *(unsigned*)&h;
}

// m16n8k16 fp16 MMA, fp32 accumulate
__device__ __forceinline__ void mma16816(float* d, uint4 a,
                                         unsigned b0, unsigned b1) {
    asm volatile(
        "mma.sync.aligned.m16n8k16.row.col.f32.f16.f16.f32 "
        "{%0,%1,%2,%3},{%4,%5,%6,%7},{%8,%9},{%0,%1,%2,%3};"
        : "+f"(d[0]), "+f"(d[1]), "+f"(d[2]), "+f"(d[3])
        : "r"(a.x), "r"(a.y), "r"(a.z), "r"(a.w), "r"(b0), "r"(b1));
}

// ---------------------------------------------------------------------------
// Prep: build A fragments g_wfrag[s][mt*4+kt][lane] from deform_w with BN
// scale folded, o padded 36->48 with zeros. Also fills g_bias.
// Fragment layout (m16n8k16 .f16 row-major A), lane = g*4+tig:
//   x = {W[mt*16+g   ][kt*16+2tig], W[..][+1]}
//   y = {W[mt*16+g+8 ][kt*16+2tig], W[..][+1]}
//   z = {W[mt*16+g   ][kt*16+2tig+8], W[..][+9]}
//   w = {W[mt*16+g+8 ][kt*16+2tig+8], W[..][+9]}
// ---------------------------------------------------------------------------
__global__ void prep_frag_kernel(const float* __restrict__ dw,
                                 const float* __restrict__ gamma,
                                 const float* __restrict__ beta,
                                 const float* __restrict__ mean,
                                 const float* __restrict__ var)
{
    int idx = blockIdx.x * 256 + threadIdx.x;
    if (idx < C2) {
        float s = gamma[idx] * rsqrtf(var[idx] + 1e-5f);
        g_bias[idx] = beta[idx] - mean[idx] * s;
    }
    if (idx >= 18 * 12 * 32) return;

    int lane = idx & 31;
    int fi = idx >> 5;
    int s  = fi / 12;
    int r  = fi % 12;
    int mt = r >> 2, kt = r & 3;
    int t  = s >> 1, dg = s & 1;
    int g = lane >> 2, tig = lane & 3;

    int o0 = mt * 16 + g;
    int o1 = o0 + 8;
    int c0 = kt * 16 + 2 * tig;

    auto W = [&](int o, int c) -> float {
        if (o >= C2) return 0.f;
        float sc = gamma[o] * rsqrtf(var[o] + 1e-5f);
        return dw[(o * C1 + dg * 64 + c) * 9 + t] * sc;
    };

    uint4 v;
    v.x = h2pack(W(o0, c0),     W(o0, c0 + 1));
    v.y = h2pack(W(o1, c0),     W(o1, c0 + 1));
    v.z = h2pack(W(o0, c0 + 8), W(o0, c0 + 9));
    v.w = h2pack(W(o1, c0 + 8), W(o1, c0 + 9));
    g_wfrag[idx] = v;
}

// ---------------------------------------------------------------------------
// Pack x [N,C,H,W] fp32 -> g_xh [N][cg=16][H,W] fp16, 8 channels per uint4.
// ---------------------------------------------------------------------------
__global__ __launch_bounds__(256) void pack_kernel(const float* __restrict__ x)
{
    int idx = blockIdx.x * 256 + threadIdx.x;
    int cg  = blockIdx.y;
    int n   = blockIdx.z;

    const float* xb = x + ((size_t)n * C1 + cg * 8) * HW + idx;
    unsigned w[4];
#pragma unroll
    for (int i = 0; i < 4; i++)
        w[i] = h2pack(xb[(2 * i) * HW], xb[(2 * i + 1) * HW]);
    g_xh[((size_t)n * 16 + cg) * HW + idx] = make_uint4(w[0], w[1], w[2], w[3]);
}

// ---------------------------------------------------------------------------
// Offset-generating grouped conv (groups=4, VALID, 3x3) — unchanged.
// ---------------------------------------------------------------------------
__global__ __launch_bounds__(192) void offset_conv_kernel(
    const float* __restrict__ x, const float* __restrict__ cw)
{
    __shared__ float  sx[16 * 14 * 34];
    __shared__ float4 wsv[32 * 9 * 3];

    int n = blockIdx.z >> 2;
    int g = blockIdx.z & 3;
    int x0 = blockIdx.x * 32;
    int y0 = blockIdx.y * 12;
    int tid = threadIdx.x;

    float* wsf = (float*)wsv;
    for (int idx = tid; idx < 32 * 9 * 12; idx += 192) {
        int o = idx % 12; int rem = idx / 12;
        int tap = rem % 9; int ci = rem / 9;
        wsf[idx] = (o < 9) ? cw[((g * 9 + o) * 32 + ci) * 9 + tap] : 0.f;
    }

    int lx = tid & 31, ly = tid >> 5;
    float acc[18];
#pragma unroll
    for (int o = 0; o < 18; o++) acc[o] = 0.f;

    for (int chunk = 0; chunk < 2; chunk++) {
        __syncthreads();
        const float* xb = x + ((size_t)n * C1 + g * 32 + chunk * 16) * HW;
        for (int idx = tid; idx < 16 * 14 * 34; idx += 192) {
            int ci = idx / 476;
            int r  = (idx % 476) / 34;
            int col = idx % 34;
            int gy = y0 + r, gx = x0 + col;
            float v = 0.f;
            if (gy < Hh && gx < Ww) v = xb[ci * HW + gy * Ww + gx];
            sx[idx] = v;
        }
        __syncthreads();

        for (int ci = 0; ci < 16; ci++) {
            int base = ci * 476 + ly * 34 + lx;
            const float4* wp = wsv + ((chunk * 16 + ci) * 9) * 3;
#pragma unroll
            for (int tap = 0; tap < 9; tap++) {
                int i = tap / 3, j = tap % 3;
                float va = sx[base + i * 34 + j];
                float vb = sx[base + (i + 6) * 34 + j];
                float4 w0 = wp[tap * 3 + 0];
                float4 w1 = wp[tap * 3 + 1];
                float4 w2 = wp[tap * 3 + 2];
                acc[0] = fmaf(va, w0.x, acc[0]);
                acc[1] = fmaf(va, w0.y, acc[1]);
                acc[2] = fmaf(va, w0.z, acc[2]);
                acc[3] = fmaf(va, w0.w, acc[3]);
                acc[4] = fmaf(va, w1.x, acc[4]);
                acc[5] = fmaf(va, w1.y, acc[5]);
                acc[6] = fmaf(va, w1.z, acc[6]);
                acc[7] = fmaf(va, w1.w, acc[7]);
                acc[8] = fmaf(va, w2.x, acc[8]);
                acc[9]  = fmaf(vb, w0.x, acc[9]);
                acc[10] = fmaf(vb, w0.y, acc[10]);
                acc[11] = fmaf(vb, w0.z, acc[11]);
                acc[12] = fmaf(vb, w0.w, acc[12]);
                acc[13] = fmaf(vb, w1.x, acc[13]);
                acc[14] = fmaf(vb, w1.y, acc[14]);
                acc[15] = fmaf(vb, w1.z, acc[15]);
                acc[16] = fmaf(vb, w1.w, acc[16]);
                acc[17] = fmaf(vb, w2.x, acc[17]);
            }
        }
    }

    int xx = x0 + lx;
    int ya = y0 + ly;
    int yb = y0 + ly + 6;
    if (xx < WO) {
        float* op = g_offset + ((size_t)n * C2 + g * 9) * HWO;
#pragma unroll
        for (int o = 0; o < 9; o++)
            op[o * HWO + ya * WO + xx] = acc[o];
        if (yb < HO) {
#pragma unroll
            for (int o = 0; o < 9; o++)
                op[o * HWO + yb * WO + xx] = acc[9 + o];
        }
    }
}

// ---------------------------------------------------------------------------
struct Ctx {
    int o00, o01, o10, o11;
    float W00, W01, W10, W11;
};

__device__ __forceinline__ Ctx make_ctx(int yy, int xx, int i, int j,
                                        float dy, float dx)
{
    Ctx c;
    float py = (float)(yy + i) + dy;
    float px = (float)(xx + j) + dx;
    float fy0 = floorf(py), fx0 = floorf(px);
    float wy1 = py - fy0, wx1 = px - fx0;
    float wy0 = 1.f - wy1, wx0 = 1.f - wx1;

    bool vy0 = (fy0       >= 0.f) && (fy0       <= (float)(Hh - 1));
    bool vy1 = (fy0 + 1.f >= 0.f) && (fy0 + 1.f <= (float)(Hh - 1));
    bool vx0 = (fx0       >= 0.f) && (fx0       <= (float)(Ww - 1));
    bool vx1 = (fx0 + 1.f >= 0.f) && (fx0 + 1.f <= (float)(Ww - 1));

    int y0i = (int)fy0, x0i = (int)fx0;
    int y0c = min(max(y0i,     0), Hh - 1);
    int y1c = min(max(y0i + 1, 0), Hh - 1);
    int x0c = min(max(x0i,     0), Ww - 1);
    int x1c = min(max(x0i + 1, 0), Ww - 1);

    c.W00 = wy0 * wx0 * ((vy0 && vx0) ? 1.f : 0.f);
    c.W01 = wy0 * wx1 * ((vy0 && vx1) ? 1.f : 0.f);
    c.W10 = wy1 * wx0 * ((vy1 && vx0) ? 1.f : 0.f);
    c.W11 = wy1 * wx1 * ((vy1 && vx1) ? 1.f : 0.f);

    c.o00 = y0c * Ww + x0c; c.o01 = y0c * Ww + x1c;
    c.o10 = y1c * Ww + x0c; c.o11 = y1c * Ww + x1c;
    return c;
}

// ---------------------------------------------------------------------------
// Deformable conv + folded BN + Mish via tensor cores.
// Block = 128 px, 4 warps. Per stage s=(tap,dg): thread tid samples pixel
// (blockbase+tid)'s 64 channels -> fp16 V[px][c] in smem (144B rows).
// Each warp MMAs its own 32-px slice: D[48o x 32px] += W[48o x 64c]*V.
// Warp-private data flow => __syncwarp only.
// ---------------------------------------------------------------------------
__global__ __launch_bounds__(128, 3) void deform_kernel(float* __restrict__ out)
{
    __shared__ __align__(16) char vsm[128 * 144];   // V fp16 [128px][72 halves]

    int tid  = threadIdx.x;
    int warp = tid >> 5, lane = tid & 31;
    int g = lane >> 2, tig = lane & 3;
    int n = blockIdx.y;
    int blockbase = blockIdx.x * 128;

    int ps = min(blockbase + tid, HWO - 1);
    int ys = ps / WO, xs = ps % WO;

    const uint4* xh  = g_xh + (size_t)n * 16 * HW;
    const float* off = g_offset + (size_t)n * C2 * HWO + ps;

    float acc[3][4][4];
#pragma unroll
    for (int mt = 0; mt < 3; mt++)
#pragma unroll
        for (int nt = 0; nt < 4; nt++)
#pragma unroll
            for (int i = 0; i < 4; i++) acc[mt][nt][i] = 0.f;

    char* myrow = vsm + (size_t)tid * 144;

    for (int s = 0; s < 18; s++) {
        int t = s >> 1, dg = s & 1;
        int ti = t / 3, tj = t % 3;

        // A fragments for this stage (same for all warps)
        uint4 af[12];
#pragma unroll
        for (int f = 0; f < 12; f++)
            af[f] = __ldg(&g_wfrag[(s * 12 + f) * 32 + lane]);

        // ---- sampling: 64 channels of current dg for pixel ps
        float dy = off[(dg * 18 + t * 2    ) * HWO];
        float dx = off[(dg * 18 + t * 2 + 1) * HWO];
        Ctx C = make_ctx(ys, xs, ti, tj, dy, dx);
        ull W00p = pack2(C.W00, C.W00), W01p = pack2(C.W01, C.W01);
        ull W10p = pack2(C.W10, C.W10), W11p = pack2(C.W11, C.W11);

#pragma unroll 4
        for (int cg = 0; cg < 8; cg++) {
            const uint4* pc = xh + (size_t)(dg * 8 + cg) * HW;
            uint4 q00 = __ldg(pc + C.o00);
            uint4 q01 = __ldg(pc + C.o01);
            uint4 q10 = __ldg(pc + C.o10);
            uint4 q11 = __ldg(pc + C.o11);
            const unsigned* u00 = (const unsigned*)&q00;
            const unsigned* u01 = (const unsigned*)&q01;
            const unsigned* u10 = (const unsigned*)&q10;
            const unsigned* u11 = (const unsigned*)&q11;
            uint4 hv;
            unsigned* hp = (unsigned*)&hv;
#pragma unroll
            for (int i = 0; i < 4; i++) {
                float2 f00 = __half22float2(*(const __half2*)&u00[i]);
                float2 f01 = __half22float2(*(const __half2*)&u01[i]);
                float2 f10 = __half22float2(*(const __half2*)&u10[i]);
                float2 f11 = __half22float2(*(const __half2*)&u11[i]);
                ull v = fma2(W00p, pack2(f00.x, f00.y),
                        fma2(W01p, pack2(f01.x, f01.y),
                        fma2(W10p, pack2(f10.x, f10.y),
                        mul2(W11p, pack2(f11.x, f11.y)))));
                hp[i] = h2pack(lo2(v), hi2(v));
            }
            *(uint4*)(myrow + cg * 16) = hv;
        }
        __syncwarp();

        // ---- MMA: warp's 32-px slice
#pragma unroll
        for (int nt = 0; nt < 4; nt++) {
            const char* rb = vsm + (size_t)(warp * 32 + nt * 8 + g) * 144
                           + tig * 4;
            unsigned b[8];
#pragma unroll
            for (int kt = 0; kt < 4; kt++) {
                b[2 * kt]     = *(const unsigned*)(rb + kt * 32);
                b[2 * kt + 1] = *(const unsigned*)(rb + kt * 32 + 16);
            }
#pragma unroll
            for (int mt = 0; mt < 3; mt++)
#pragma unroll
                for (int kt = 0; kt < 4; kt++)
                    mma16816(acc[mt][nt], af[mt * 4 + kt],
                             b[2 * kt], b[2 * kt + 1]);
        }
        __syncwarp();
    }

    // ---- epilogue: bias + Mish
    float* ob = out + (size_t)n * C2 * HWO;
#pragma unroll
    for (int mt = 0; mt < 3; mt++) {
        int o0 = mt * 16 + g;
        int o1 = o0 + 8;
#pragma unroll
        for (int nt = 0; nt < 4; nt++) {
            int px = blockbase + warp * 32 + nt * 8 + 2 * tig;
            const float* a = acc[mt][nt];
#pragma unroll
            for (int h = 0; h < 2; h++) {       // h=0 -> o0, h=1 -> o1
                int o = h ? o1 : o0;
                if (o < C2) {
                    float b = __ldg(g_bias + o);
#pragma unroll
                    for (int e = 0; e < 2; e++) {
                        int p = px + e;
                        if (p < HWO) {
                            float z = a[h * 2 + e] + b;
                            float sp = (z > 20.f) ? z : log1pf(expf(z));
                            ob[(size_t)o * HWO + p] = z * tanhf(sp);
                        }
                    }
                }
            }
        }
    }
}

// ---------------------------------------------------------------------------
extern "C" void kernel_launch(void* const* d_in, const int* in_sizes, int n_in,
                              void* d_out, int out_size)
{
    const float* x        = (const float*)d_in[0];
    const float* conv_w   = (const float*)d_in[1];
    const float* deform_w = (const float*)d_in[2];
    const float* bn_gamma = (const float*)d_in[3];
    const float* bn_beta  = (const float*)d_in[4];
    const float* bn_mean  = (const float*)d_in[5];
    const float* bn_var   = (const float*)d_in[6];
    float* out = (float*)d_out;

    prep_frag_kernel<<<27, 256>>>(deform_w, bn_gamma, bn_beta, bn_mean, bn_var);

    pack_kernel<<<dim3(HW / 256, 16, NN), 256>>>(x);

    offset_conv_kernel<<<dim3(6, 16, 16), 192>>>(x, conv_w);

    deform_kernel<<<dim3((HWO + 127) / 128, NN), 128>>>(out);
}

// round 12
// speedup vs baseline: 2.6926x; 1.0789x over previous
#include <cuda_runtime.h>
#include <cuda_fp16.h>
#include <math.h>

#define NN 4
#define C1 128
#define C2 36
#define Hh 192
#define Ww 192
#define HO 190
#define WO 190
#define HW (Hh*Ww)
#define HWO (HO*WO)

typedef unsigned long long ull;

// Scratch (device globals: allocation-free rule)
__device__ float g_offset[NN*C2*HWO];    // offset conv output [N,36,HO,WO]
__device__ float g_bias[C2];             // folded BN bias
__device__ uint4 g_xh[(size_t)NN*16*HW]; // x fp16, 8ch packed [n][cg=16][h][w]
__device__ uint4 g_wfrag[18*12*32];      // A fragments [s=t*2+dg][mt*4+kt][lane]

// ---- packed f32x2 helpers -------------------------------------------------
__device__ __forceinline__ ull fma2(ull a, ull b, ull c) {
    ull d; asm("fma.rn.f32x2 %0,%1,%2,%3;" : "=l"(d) : "l"(a), "l"(b), "l"(c));
    return d;
}
__device__ __forceinline__ ull mul2(ull a, ull b) {
    ull d; asm("mul.rn.f32x2 %0,%1,%2;" : "=l"(d) : "l"(a), "l"(b));
    return d;
}
__device__ __forceinline__ ull pack2(float x, float y) {
    ull d; asm("mov.b64 %0,{%1,%2};" : "=l"(d) : "f"(x), "f"(y));
    return d;
}
__device__ __forceinline__ float lo2(ull a) { return __uint_as_float((unsigned)a); }
__device__ __forceinline__ float hi2(ull a) { return __uint_as_float((unsigned)(a >> 32)); }

__device__ __forceinline__ unsigned h2pack(float a, float b) {
    __half2 h = __floats2half2_rn(a, b);
    return *(unsigned*)&h;
}

// m16n8k16 fp16 MMA, fp32 accumulate
__device__ __forceinline__ void mma16816(float* d, uint4 a,
                                         unsigned b0, unsigned b1) {
    asm volatile(
        "mma.sync.aligned.m16n8k16.row.col.f32.f16.f16.f32 "
        "{%0,%1,%2,%3},{%4,%5,%6,%7},{%8,%9},{%0,%1,%2,%3};"
        : "+f"(d[0]), "+f"(d[1]), "+f"(d[2]), "+f"(d[3])
        : "r"(a.x), "r"(a.y), "r"(a.z), "r"(a.w), "r"(b0), "r"(b1));
}

// ---------------------------------------------------------------------------
// Prep: build A fragments + bias (see round-11 layout notes).
// ---------------------------------------------------------------------------
__global__ void prep_frag_kernel(const float* __restrict__ dw,
                                 const float* __restrict__ gamma,
                                 const float* __restrict__ beta,
                                 const float* __restrict__ mean,
                                 const float* __restrict__ var)
{
    int idx = blockIdx.x * 256 + threadIdx.x;
    if (idx < C2) {
        float s = gamma[idx] * rsqrtf(var[idx] + 1e-5f);
        g_bias[idx] = beta[idx] - mean[idx] * s;
    }
    if (idx >= 18 * 12 * 32) return;

    int lane = idx & 31;
    int fi = idx >> 5;
    int s  = fi / 12;
    int r  = fi % 12;
    int mt = r >> 2, kt = r & 3;
    int t  = s >> 1, dg = s & 1;
    int g = lane >> 2, tig = lane & 3;

    int o0 = mt * 16 + g;
    int o1 = o0 + 8;
    int c0 = kt * 16 + 2 * tig;

    auto W = [&](int o, int c) -> float {
        if (o >= C2) return 0.f;
        float sc = gamma[o] * rsqrtf(var[o] + 1e-5f);
        return dw[(o * C1 + dg * 64 + c) * 9 + t] * sc;
    };

    uint4 v;
    v.x = h2pack(W(o0, c0),     W(o0, c0 + 1));
    v.y = h2pack(W(o1, c0),     W(o1, c0 + 1));
    v.z = h2pack(W(o0, c0 + 8), W(o0, c0 + 9));
    v.w = h2pack(W(o1, c0 + 8), W(o1, c0 + 9));
    g_wfrag[idx] = v;
}

// ---------------------------------------------------------------------------
// Pack x [N,C,H,W] fp32 -> g_xh [N][cg=16][H,W] fp16, 8 channels per uint4.
// ---------------------------------------------------------------------------
__global__ __launch_bounds__(256) void pack_kernel(const float* __restrict__ x)
{
    int idx = blockIdx.x * 256 + threadIdx.x;
    int cg  = blockIdx.y;
    int n   = blockIdx.z;

    const float* xb = x + ((size_t)n * C1 + cg * 8) * HW + idx;
    unsigned w[4];
#pragma unroll
    for (int i = 0; i < 4; i++)
        w[i] = h2pack(xb[(2 * i) * HW], xb[(2 * i + 1) * HW]);
    g_xh[((size_t)n * 16 + cg) * HW + idx] = make_uint4(w[0], w[1], w[2], w[3]);
}

// ---------------------------------------------------------------------------
// Offset-generating grouped conv (groups=4, VALID, 3x3, stride 1)
// 32x12 output tile, 2 rows/thread packed into f32x2 accumulators (FFMA2).
// Weights duplicated into smem as ull (both halves equal), padded 9->10.
// ---------------------------------------------------------------------------
__global__ __launch_bounds__(192) void offset_conv_kernel(
    const float* __restrict__ x, const float* __restrict__ cw)
{
    __shared__ float sx[16 * 14 * 34];     // 30464 B
    __shared__ ull   ws2[16 * 9 * 10];     // 11520 B (dup weights, padded)

    int n = blockIdx.z >> 2;
    int g = blockIdx.z & 3;
    int x0 = blockIdx.x * 32;
    int y0 = blockIdx.y * 12;
    int tid = threadIdx.x;

    int lx = tid & 31, ly = tid >> 5;
    ull acc2[9];
#pragma unroll
    for (int o = 0; o < 9; o++) acc2[o] = 0ull;

    for (int chunk = 0; chunk < 2; chunk++) {
        __syncthreads();
        const float* xb = x + ((size_t)n * C1 + g * 32 + chunk * 16) * HW;
        for (int idx = tid; idx < 16 * 14 * 34; idx += 192) {
            int ci = idx / 476;
            int r  = (idx % 476) / 34;
            int col = idx % 34;
            int gy = y0 + r, gx = x0 + col;
            float v = 0.f;
            if (gy < Hh && gx < Ww) v = xb[ci * HW + gy * Ww + gx];
            sx[idx] = v;
        }
        // stage duplicated weights for this chunk
        for (int idx = tid; idx < 16 * 9 * 10; idx += 192) {
            int o = idx % 10; int rem = idx / 10;
            int tap = rem % 9; int ci = rem / 9;
            float w = 0.f;
            if (o < 9)
                w = cw[((g * 9 + o) * 32 + chunk * 16 + ci) * 9 + tap];
            ws2[idx] = pack2(w, w);
        }
        __syncthreads();

        for (int ci = 0; ci < 16; ci++) {
            int base = ci * 476 + ly * 34 + lx;
#pragma unroll
            for (int tap = 0; tap < 9; tap++) {
                int i = tap / 3, j = tap % 3;
                float va = sx[base + i * 34 + j];
                float vb = sx[base + (i + 6) * 34 + j];
                ull v2 = pack2(va, vb);
                const ulonglong2* wr =
                    (const ulonglong2*)(ws2 + (ci * 9 + tap) * 10);
                ulonglong2 w0 = wr[0], w1 = wr[1], w2 = wr[2], w3 = wr[3];
                ull w8 = *(const ull*)(wr + 4);
                acc2[0] = fma2(v2, w0.x, acc2[0]);
                acc2[1] = fma2(v2, w0.y, acc2[1]);
                acc2[2] = fma2(v2, w1.x, acc2[2]);
                acc2[3] = fma2(v2, w1.y, acc2[3]);
                acc2[4] = fma2(v2, w2.x, acc2[4]);
                acc2[5] = fma2(v2, w2.y, acc2[5]);
                acc2[6] = fma2(v2, w3.x, acc2[6]);
                acc2[7] = fma2(v2, w3.y, acc2[7]);
                acc2[8] = fma2(v2, w8,   acc2[8]);
            }
        }
    }

    int xx = x0 + lx;
    int ya = y0 + ly;
    int yb = y0 + ly + 6;
    if (xx < WO) {
        float* op = g_offset + ((size_t)n * C2 + g * 9) * HWO;
#pragma unroll
        for (int o = 0; o < 9; o++)
            op[o * HWO + ya * WO + xx] = lo2(acc2[o]);
        if (yb < HO) {
#pragma unroll
            for (int o = 0; o < 9; o++)
                op[o * HWO + yb * WO + xx] = hi2(acc2[o]);
        }
    }
}

// ---------------------------------------------------------------------------
struct Ctx {
    int o00, o01, o10, o11;
    float W00, W01, W10, W11;
};

__device__ __forceinline__ Ctx make_ctx(int yy, int xx, int i, int j,
                                        float dy, float dx)
{
    Ctx c;
    float py = (float)(yy + i) + dy;
    float px = (float)(xx + j) + dx;
    float fy0 = floorf(py), fx0 = floorf(px);
    float wy1 = py - fy0, wx1 = px - fx0;
    float wy0 = 1.f - wy1, wx0 = 1.f - wx1;

    bool vy0 = (fy0       >= 0.f) && (fy0       <= (float)(Hh - 1));
    bool vy1 = (fy0 + 1.f >= 0.f) && (fy0 + 1.f <= (float)(Hh - 1));
    bool vx0 = (fx0       >= 0.f) && (fx0       <= (float)(Ww - 1));
    bool vx1 = (fx0 + 1.f >= 0.f) && (fx0 + 1.f <= (float)(Ww - 1));

    int y0i = (int)fy0, x0i = (int)fx0;
    int y0c = min(max(y0i,     0), Hh - 1);
    int y1c = min(max(y0i + 1, 0), Hh - 1);
    int x0c = min(max(x0i,     0), Ww - 1);
    int x1c = min(max(x0i + 1, 0), Ww - 1);

    c.W00 = wy0 * wx0 * ((vy0 && vx0) ? 1.f : 0.f);
    c.W01 = wy0 * wx1 * ((vy0 && vx1) ? 1.f : 0.f);
    c.W10 = wy1 * wx0 * ((vy1 && vx0) ? 1.f : 0.f);
    c.W11 = wy1 * wx1 * ((vy1 && vx1) ? 1.f : 0.f);

    c.o00 = y0c * Ww + x0c; c.o01 = y0c * Ww + x1c;
    c.o10 = y1c * Ww + x0c; c.o11 = y1c * Ww + x1c;
    return c;
}

// ---------------------------------------------------------------------------
// Deformable conv + folded BN + Mish via tensor cores (round-11 structure,
// A-fragments loaded inside the MMA loop to cut register pressure -> occ 4).
// ---------------------------------------------------------------------------
__global__ __launch_bounds__(128, 4) void deform_kernel(float* __restrict__ out)
{
    __shared__ __align__(16) char vsm[128 * 144];   // V fp16 [128px][72 halves]

    int tid  = threadIdx.x;
    int warp = tid >> 5, lane = tid & 31;
    int g = lane >> 2, tig = lane & 3;
    int n = blockIdx.y;
    int blockbase = blockIdx.x * 128;

    int ps = min(blockbase + tid, HWO - 1);
    int ys = ps / WO, xs = ps % WO;

    const uint4* xh  = g_xh + (size_t)n * 16 * HW;
    const float* off = g_offset + (size_t)n * C2 * HWO + ps;

    float acc[3][4][4];
#pragma unroll
    for (int mt = 0; mt < 3; mt++)
#pragma unroll
        for (int nt = 0; nt < 4; nt++)
#pragma unroll
            for (int i = 0; i < 4; i++) acc[mt][nt][i] = 0.f;

    char* myrow = vsm + (size_t)tid * 144;

    for (int s = 0; s < 18; s++) {
        int t = s >> 1, dg = s & 1;
        int ti = t / 3, tj = t % 3;

        // ---- sampling: 64 channels of current dg for pixel ps
        float dy = off[(dg * 18 + t * 2    ) * HWO];
        float dx = off[(dg * 18 + t * 2 + 1) * HWO];
        Ctx C = make_ctx(ys, xs, ti, tj, dy, dx);
        ull W00p = pack2(C.W00, C.W00), W01p = pack2(C.W01, C.W01);
        ull W10p = pack2(C.W10, C.W10), W11p = pack2(C.W11, C.W11);

#pragma unroll 4
        for (int cg = 0; cg < 8; cg++) {
            const uint4* pc = xh + (size_t)(dg * 8 + cg) * HW;
            uint4 q00 = __ldg(pc + C.o00);
            uint4 q01 = __ldg(pc + C.o01);
            uint4 q10 = __ldg(pc + C.o10);
            uint4 q11 = __ldg(pc + C.o11);
            const unsigned* u00 = (const unsigned*)&q00;
            const unsigned* u01 = (const unsigned*)&q01;
            const unsigned* u10 = (const unsigned*)&q10;
            const unsigned* u11 = (const unsigned*)&q11;
            uint4 hv;
            unsigned* hp = (unsigned*)&hv;
#pragma unroll
            for (int i = 0; i < 4; i++) {
                float2 f00 = __half22float2(*(const __half2*)&u00[i]);
                float2 f01 = __half22float2(*(const __half2*)&u01[i]);
                float2 f10 = __half22float2(*(const __half2*)&u10[i]);
                float2 f11 = __half22float2(*(const __half2*)&u11[i]);
                ull v = fma2(W00p, pack2(f00.x, f00.y),
                        fma2(W01p, pack2(f01.x, f01.y),
                        fma2(W10p, pack2(f10.x, f10.y),
                        mul2(W11p, pack2(f11.x, f11.y)))));
                hp[i] = h2pack(lo2(v), hi2(v));
            }
            *(uint4*)(myrow + cg * 16) = hv;
        }
        __syncwarp();

        // ---- MMA: warp's 32-px slice (A-fragments loaded in-loop)
#pragma unroll
        for (int nt = 0; nt < 4; nt++) {
            const char* rb = vsm + (size_t)(warp * 32 + nt * 8 + g) * 144
                           + tig * 4;
            unsigned b[8];
#pragma unroll
            for (int kt = 0; kt < 4; kt++) {
                b[2 * kt]     = *(const unsigned*)(rb + kt * 32);
                b[2 * kt + 1] = *(const unsigned*)(rb + kt * 32 + 16);
            }
#pragma unroll
            for (int mt = 0; mt < 3; mt++) {
#pragma unroll
                for (int kt = 0; kt < 4; kt++) {
                    uint4 a = __ldg(&g_wfrag[(s * 12 + mt * 4 + kt) * 32 + lane]);
                    mma16816(acc[mt][nt], a, b[2 * kt], b[2 * kt + 1]);
                }
            }
        }
        __syncwarp();
    }

    // ---- epilogue: bias + Mish
    float* ob = out + (size_t)n * C2 * HWO;
#pragma unroll
    for (int mt = 0; mt < 3; mt++) {
        int o0 = mt * 16 + g;
        int o1 = o0 + 8;
#pragma unroll
        for (int nt = 0; nt < 4; nt++) {
            int px = blockbase + warp * 32 + nt * 8 + 2 * tig;
            const float* a = acc[mt][nt];
#pragma unroll
            for (int h = 0; h < 2; h++) {
                int o = h ? o1 : o0;
                if (o < C2) {
                    float b = __ldg(g_bias + o);
#pragma unroll
                    for (int e = 0; e < 2; e++) {
                        int p = px + e;
                        if (p < HWO) {
                            float z = a[h * 2 + e] + b;
                            float sp = (z > 20.f) ? z : log1pf(expf(z));
                            ob[(size_t)o * HWO + p] = z * tanhf(sp);
                        }
                    }
                }
            }
        }
    }
}

// ---------------------------------------------------------------------------
extern "C" void kernel_launch(void* const* d_in, const int* in_sizes, int n_in,
                              void* d_out, int out_size)
{
    const float* x        = (const float*)d_in[0];
    const float* conv_w   = (const float*)d_in[1];
    const float* deform_w = (const float*)d_in[2];
    const float* bn_gamma = (const float*)d_in[3];
    const float* bn_beta  = (const float*)d_in[4];
    const float* bn_mean  = (const float*)d_in[5];
    const float* bn_var   = (const float*)d_in[6];
    float* out = (float*)d_out;

    prep_frag_kernel<<<27, 256>>>(deform_w, bn_gamma, bn_beta, bn_mean, bn_var);

    pack_kernel<<<dim3(HW / 256, 16, NN), 256>>>(x);

    offset_conv_kernel<<<dim3(6, 16, 16), 192>>>(x, conv_w);

    deform_kernel<<<dim3((HWO + 127) / 128, NN), 128>>>(out);
}

// round 13
// speedup vs baseline: 3.8987x; 1.4479x over previous
#include <cuda_runtime.h>
#include <cuda_fp16.h>
#include <math.h>

#define NN 4
#define C1 128
#define C2 36
#define Hh 192
#define Ww 192
#define HO 190
#define WO 190
#define HW (Hh*Ww)
#define HWO (HO*WO)

typedef unsigned long long ull;

// Scratch (device globals: allocation-free rule)
__device__ float g_offset[NN*C2*HWO];    // offset conv output [N,36,HO,WO]
__device__ float g_bias[C2];             // folded BN bias
__device__ uint4 g_xh[(size_t)NN*16*HW]; // x fp16, 8ch packed [n][cg=16][h][w]
__device__ uint4 g_wfrag[18*12*32];      // deform A frags [s][mt*4+kt][lane]
__device__ uint4 g_ofrag[4*9*2*32];      // offset A frags [(g*9+t)*2+kt][lane]

// ---- packed f32x2 helpers -------------------------------------------------
__device__ __forceinline__ ull fma2(ull a, ull b, ull c) {
    ull d; asm("fma.rn.f32x2 %0,%1,%2,%3;" : "=l"(d) : "l"(a), "l"(b), "l"(c));
    return d;
}
__device__ __forceinline__ ull mul2(ull a, ull b) {
    ull d; asm("mul.rn.f32x2 %0,%1,%2;" : "=l"(d) : "l"(a), "l"(b));
    return d;
}
__device__ __forceinline__ ull pack2(float x, float y) {
    ull d; asm("mov.b64 %0,{%1,%2};" : "=l"(d) : "f"(x), "f"(y));
    return d;
}
__device__ __forceinline__ float lo2(ull a) { return __uint_as_float((unsigned)a); }
__device__ __forceinline__ float hi2(ull a) { return __uint_as_float((unsigned)(a >> 32)); }

__device__ __forceinline__ unsigned h2pack(float a, float b) {
    __half2 h = __floats2half2_rn(a, b);
    return *(unsigned*)&h;
}

// m16n8k16 fp16 MMA, fp32 accumulate
__device__ __forceinline__ void mma16816(float* d, uint4 a,
                                         unsigned b0, unsigned b1) {
    asm volatile(
        "mma.sync.aligned.m16n8k16.row.col.f32.f16.f16.f32 "
        "{%0,%1,%2,%3},{%4,%5,%6,%7},{%8,%9},{%0,%1,%2,%3};"
        : "+f"(d[0]), "+f"(d[1]), "+f"(d[2]), "+f"(d[3])
        : "r"(a.x), "r"(a.y), "r"(a.z), "r"(a.w), "r"(b0), "r"(b1));
}

// ---------------------------------------------------------------------------
// Prep: deform A fragments (BN-folded, o pad 36->48), offset-conv A fragments
// (o pad 9->16 per group), bias.
// ---------------------------------------------------------------------------
__global__ void prep_frag_kernel(const float* __restrict__ dw,
                                 const float* __restrict__ cwp,
                                 const float* __restrict__ gamma,
                                 const float* __restrict__ beta,
                                 const float* __restrict__ mean,
                                 const float* __restrict__ var)
{
    int idx = blockIdx.x * 256 + threadIdx.x;
    if (idx < C2) {
        float s = gamma[idx] * rsqrtf(var[idx] + 1e-5f);
        g_bias[idx] = beta[idx] - mean[idx] * s;
    }

    if (idx < 18 * 12 * 32) {
        int lane = idx & 31;
        int fi = idx >> 5;
        int s  = fi / 12;
        int r  = fi % 12;
        int mt = r >> 2, kt = r & 3;
        int t  = s >> 1, dg = s & 1;
        int g = lane >> 2, tig = lane & 3;

        int o0 = mt * 16 + g;
        int o1 = o0 + 8;
        int c0 = kt * 16 + 2 * tig;

        auto W = [&](int o, int c) -> float {
            if (o >= C2) return 0.f;
            float sc = gamma[o] * rsqrtf(var[o] + 1e-5f);
            return dw[(o * C1 + dg * 64 + c) * 9 + t] * sc;
        };

        uint4 v;
        v.x = h2pack(W(o0, c0),     W(o0, c0 + 1));
        v.y = h2pack(W(o1, c0),     W(o1, c0 + 1));
        v.z = h2pack(W(o0, c0 + 8), W(o0, c0 + 9));
        v.w = h2pack(W(o1, c0 + 8), W(o1, c0 + 9));
        g_wfrag[idx] = v;
    }

    int idx2 = idx - 18 * 12 * 32;
    if (idx2 >= 0 && idx2 < 4 * 9 * 2 * 32) {
        int lane = idx2 & 31;
        int fi = idx2 >> 5;             // (g*9+t)*2 + kt
        int kt = fi & 1;
        int gt = fi >> 1;
        int g = gt / 9, t = gt % 9;
        int gq = lane >> 2, tig = lane & 3;

        int o0 = gq, o1 = gq + 8;
        int c0 = kt * 16 + 2 * tig;

        auto Wv = [&](int o, int c) -> float {
            if (o >= 9) return 0.f;
            return cwp[((g * 9 + o) * 32 + c) * 9 + t];
        };

        uint4 v;
        v.x = h2pack(Wv(o0, c0),     Wv(o0, c0 + 1));
        v.y = h2pack(Wv(o1, c0),     Wv(o1, c0 + 1));
        v.z = h2pack(Wv(o0, c0 + 8), Wv(o0, c0 + 9));
        v.w = h2pack(Wv(o1, c0 + 8), Wv(o1, c0 + 9));
        g_ofrag[fi * 32 + lane] = v;
    }
}

// ---------------------------------------------------------------------------
// Pack x [N,C,H,W] fp32 -> g_xh [N][cg=16][H,W] fp16, 8 channels per uint4.
// ---------------------------------------------------------------------------
__global__ __launch_bounds__(256) void pack_kernel(const float* __restrict__ x)
{
    int idx = blockIdx.x * 256 + threadIdx.x;
    int cg  = blockIdx.y;
    int n   = blockIdx.z;

    const float* xb = x + ((size_t)n * C1 + cg * 8) * HW + idx;
    unsigned w[4];
#pragma unroll
    for (int i = 0; i < 4; i++)
        w[i] = h2pack(xb[(2 * i) * HW], xb[(2 * i + 1) * HW]);
    g_xh[((size_t)n * 16 + cg) * HW + idx] = make_uint4(w[0], w[1], w[2], w[3]);
}

// ---------------------------------------------------------------------------
// Offset-generating grouped conv via tensor cores.
// Block = 128 px, 4 warps; blockIdx.y = n*4+g. Per tap: each thread copies
// its pixel's 32 group-channels (fp16 packed) to smem row (80B padded,
// conflict-free), warps MMA [16o x 32px] over k=32 (2 chunks) x 9 taps.
// ---------------------------------------------------------------------------
__global__ __launch_bounds__(128, 4) void offset_mma_kernel()
{
    __shared__ __align__(16) char vsm[128 * 80];   // [px][32 ch fp16 + pad]

    int tid  = threadIdx.x;
    int warp = tid >> 5, lane = tid & 31;
    int gq = lane >> 2, tig = lane & 3;
    int n = blockIdx.y >> 2;
    int g = blockIdx.y & 3;
    int blockbase = blockIdx.x * 128;

    int ps = min(blockbase + tid, HWO - 1);
    int ys = ps / WO, xs = ps % WO;

    const uint4* xh = g_xh + ((size_t)n * 16 + g * 4) * HW;

    float acc[4][4];
#pragma unroll
    for (int nt = 0; nt < 4; nt++)
#pragma unroll
        for (int i = 0; i < 4; i++) acc[nt][i] = 0.f;

    char* myrow = vsm + (size_t)tid * 80;

    for (int t = 0; t < 9; t++) {
        int ti = t / 3, tj = t % 3;
        int pos = (ys + ti) * Ww + (xs + tj);

#pragma unroll
        for (int cg = 0; cg < 4; cg++) {
            uint4 q = __ldg(xh + (size_t)cg * HW + pos);
            *(uint4*)(myrow + cg * 16) = q;
        }
        __syncwarp();

#pragma unroll
        for (int nt = 0; nt < 4; nt++) {
            const char* rb = vsm + (size_t)(warp * 32 + nt * 8 + gq) * 80
                           + tig * 4;
#pragma unroll
            for (int kt = 0; kt < 2; kt++) {
                unsigned b0 = *(const unsigned*)(rb + kt * 32);
                unsigned b1 = *(const unsigned*)(rb + kt * 32 + 16);
                uint4 a = __ldg(&g_ofrag[(((g * 9 + t) * 2) + kt) * 32 + lane]);
                mma16816(acc[nt], a, b0, b1);
            }
        }
        __syncwarp();
    }

    // epilogue: rows o = gq (0..7) and o = gq+8 (valid only gq==0 -> o=8)
    float* op = g_offset + ((size_t)n * C2 + g * 9) * HWO;
#pragma unroll
    for (int nt = 0; nt < 4; nt++) {
        int px = blockbase + warp * 32 + nt * 8 + 2 * tig;
#pragma unroll
        for (int e = 0; e < 2; e++) {
            int p = px + e;
            if (p < HWO) {
                op[(size_t)gq * HWO + p] = acc[nt][e];
                if (gq == 0)
                    op[(size_t)8 * HWO + p] = acc[nt][2 + e];
            }
        }
    }
}

// ---------------------------------------------------------------------------
struct Ctx {
    int o00, o01, o10, o11;
    float W00, W01, W10, W11;
};

__device__ __forceinline__ Ctx make_ctx(int yy, int xx, int i, int j,
                                        float dy, float dx)
{
    Ctx c;
    float py = (float)(yy + i) + dy;
    float px = (float)(xx + j) + dx;
    float fy0 = floorf(py), fx0 = floorf(px);
    float wy1 = py - fy0, wx1 = px - fx0;
    float wy0 = 1.f - wy1, wx0 = 1.f - wx1;

    bool vy0 = (fy0       >= 0.f) && (fy0       <= (float)(Hh - 1));
    bool vy1 = (fy0 + 1.f >= 0.f) && (fy0 + 1.f <= (float)(Hh - 1));
    bool vx0 = (fx0       >= 0.f) && (fx0       <= (float)(Ww - 1));
    bool vx1 = (fx0 + 1.f >= 0.f) && (fx0 + 1.f <= (float)(Ww - 1));

    int y0i = (int)fy0, x0i = (int)fx0;
    int y0c = min(max(y0i,     0), Hh - 1);
    int y1c = min(max(y0i + 1, 0), Hh - 1);
    int x0c = min(max(x0i,     0), Ww - 1);
    int x1c = min(max(x0i + 1, 0), Ww - 1);

    c.W00 = wy0 * wx0 * ((vy0 && vx0) ? 1.f : 0.f);
    c.W01 = wy0 * wx1 * ((vy0 && vx1) ? 1.f : 0.f);
    c.W10 = wy1 * wx0 * ((vy1 && vx0) ? 1.f : 0.f);
    c.W11 = wy1 * wx1 * ((vy1 && vx1) ? 1.f : 0.f);

    c.o00 = y0c * Ww + x0c; c.o01 = y0c * Ww + x1c;
    c.o10 = y1c * Ww + x0c; c.o11 = y1c * Ww + x1c;
    return c;
}

// ---------------------------------------------------------------------------
// Deformable conv + folded BN + Mish via tensor cores (unchanged from R12).
// ---------------------------------------------------------------------------
__global__ __launch_bounds__(128, 4) void deform_kernel(float* __restrict__ out)
{
    __shared__ __align__(16) char vsm[128 * 144];   // V fp16 [128px][72 halves]

    int tid  = threadIdx.x;
    int warp = tid >> 5, lane = tid & 31;
    int g = lane >> 2, tig = lane & 3;
    int n = blockIdx.y;
    int blockbase = blockIdx.x * 128;

    int ps = min(blockbase + tid, HWO - 1);
    int ys = ps / WO, xs = ps % WO;

    const uint4* xh  = g_xh + (size_t)n * 16 * HW;
    const float* off = g_offset + (size_t)n * C2 * HWO + ps;

    float acc[3][4][4];
#pragma unroll
    for (int mt = 0; mt < 3; mt++)
#pragma unroll
        for (int nt = 0; nt < 4; nt++)
#pragma unroll
            for (int i = 0; i < 4; i++) acc[mt][nt][i] = 0.f;

    char* myrow = vsm + (size_t)tid * 144;

    for (int s = 0; s < 18; s++) {
        int t = s >> 1, dg = s & 1;
        int ti = t / 3, tj = t % 3;

        float dy = off[(dg * 18 + t * 2    ) * HWO];
        float dx = off[(dg * 18 + t * 2 + 1) * HWO];
        Ctx C = make_ctx(ys, xs, ti, tj, dy, dx);
        ull W00p = pack2(C.W00, C.W00), W01p = pack2(C.W01, C.W01);
        ull W10p = pack2(C.W10, C.W10), W11p = pack2(C.W11, C.W11);

#pragma unroll 4
        for (int cg = 0; cg < 8; cg++) {
            const uint4* pc = xh + (size_t)(dg * 8 + cg) * HW;
            uint4 q00 = __ldg(pc + C.o00);
            uint4 q01 = __ldg(pc + C.o01);
            uint4 q10 = __ldg(pc + C.o10);
            uint4 q11 = __ldg(pc + C.o11);
            const unsigned* u00 = (const unsigned*)&q00;
            const unsigned* u01 = (const unsigned*)&q01;
            const unsigned* u10 = (const unsigned*)&q10;
            const unsigned* u11 = (const unsigned*)&q11;
            uint4 hv;
            unsigned* hp = (unsigned*)&hv;
#pragma unroll
            for (int i = 0; i < 4; i++) {
                float2 f00 = __half22float2(*(const __half2*)&u00[i]);
                float2 f01 = __half22float2(*(const __half2*)&u01[i]);
                float2 f10 = __half22float2(*(const __half2*)&u10[i]);
                float2 f11 = __half22float2(*(const __half2*)&u11[i]);
                ull v = fma2(W00p, pack2(f00.x, f00.y),
                        fma2(W01p, pack2(f01.x, f01.y),
                        fma2(W10p, pack2(f10.x, f10.y),
                        mul2(W11p, pack2(f11.x, f11.y)))));
                hp[i] = h2pack(lo2(v), hi2(v));
            }
            *(uint4*)(myrow + cg * 16) = hv;
        }
        __syncwarp();

#pragma unroll
        for (int nt = 0; nt < 4; nt++) {
            const char* rb = vsm + (size_t)(warp * 32 + nt * 8 + g) * 144
                           + tig * 4;
            unsigned b[8];
#pragma unroll
            for (int kt = 0; kt < 4; kt++) {
                b[2 * kt]     = *(const unsigned*)(rb + kt * 32);
                b[2 * kt + 1] = *(const unsigned*)(rb + kt * 32 + 16);
            }
#pragma unroll
            for (int mt = 0; mt < 3; mt++) {
#pragma unroll
                for (int kt = 0; kt < 4; kt++) {
                    uint4 a = __ldg(&g_wfrag[(s * 12 + mt * 4 + kt) * 32 + lane]);
                    mma16816(acc[mt][nt], a, b[2 * kt], b[2 * kt + 1]);
                }
            }
        }
        __syncwarp();
    }

    float* ob = out + (size_t)n * C2 * HWO;
#pragma unroll
    for (int mt = 0; mt < 3; mt++) {
        int o0 = mt * 16 + g;
        int o1 = o0 + 8;
#pragma unroll
        for (int nt = 0; nt < 4; nt++) {
            int px = blockbase + warp * 32 + nt * 8 + 2 * tig;
            const float* a = acc[mt][nt];
#pragma unroll
            for (int h = 0; h < 2; h++) {
                int o = h ? o1 : o0;
                if (o < C2) {
                    float b = __ldg(g_bias + o);
#pragma unroll
                    for (int e = 0; e < 2; e++) {
                        int p = px + e;
                        if (p < HWO) {
                            float z = a[h * 2 + e] + b;
                            float sp = (z > 20.f) ? z : log1pf(expf(z));
                            ob[(size_t)o * HWO + p] = z * tanhf(sp);
                        }
                    }
                }
            }
        }
    }
}

// ---------------------------------------------------------------------------
extern "C" void kernel_launch(void* const* d_in, const int* in_sizes, int n_in,
                              void* d_out, int out_size)
{
    const float* x        = (const float*)d_in[0];
    const float* conv_w   = (const float*)d_in[1];
    const float* deform_w = (const float*)d_in[2];
    const float* bn_gamma = (const float*)d_in[3];
    const float* bn_beta  = (const float*)d_in[4];
    const float* bn_mean  = (const float*)d_in[5];
    const float* bn_var   = (const float*)d_in[6];
    float* out = (float*)d_out;

    prep_frag_kernel<<<36, 256>>>(deform_w, conv_w,
                                  bn_gamma, bn_beta, bn_mean, bn_var);

    pack_kernel<<<dim3(HW / 256, 16, NN), 256>>>(x);

    offset_mma_kernel<<<dim3((HWO + 127) / 128, NN * 4), 128>>>();

    deform_kernel<<<dim3((HWO + 127) / 128, NN), 128>>>(out);
}